// round 4
// baseline (speedup 1.0000x reference)
#include <cuda_runtime.h>
#include <cstddef>

// Problem constants
#define HWC   65536          // H*W = 256*256
#define CCH   256            // channels
#define NBAT  4
#define NHEAD 8
#define HD    32
#define NGRP  32
#define CPG   8              // channels per group

// ---------------------------------------------------------------------------
// Scratch (static device globals — no allocation at kernel_launch time)
// ---------------------------------------------------------------------------
__device__ float g_stats[NBAT * NGRP * 2];          // mean, rstd per (b,g)
__device__ float g_wadj [NBAT * 768 * 256];         // GN-folded QKV weights
__device__ float g_badj [NBAT * 768];               // GN-folded QKV biases
__device__ float g_qkv  [(size_t)NBAT * 768 * HWC]; // q/k/v stacked, [b][768][HW]
__device__ float g_attn [(size_t)NBAT * 256 * HWC]; // attention output [b][C][HW]

// ---------------------------------------------------------------------------
// K1: GroupNorm statistics. One block per (b,g); the 8 channels of a group are
// contiguous (2 MB per group), so this is a flat contiguous reduction.
// ---------------------------------------------------------------------------
__global__ __launch_bounds__(512) void gn_stats_kernel(const float* __restrict__ q)
{
    int bg = blockIdx.x;                                  // 0..127
    const float4* base = (const float4*)(q + (size_t)bg * CPG * HWC);
    float s = 0.f, s2 = 0.f;
    for (int i = threadIdx.x; i < (CPG * HWC) / 4; i += 512) {
        float4 v = base[i];
        s  += v.x + v.y + v.z + v.w;
        s2 += v.x*v.x + v.y*v.y + v.z*v.z + v.w*v.w;
    }
    __shared__ float rs[512], rs2[512];
    rs[threadIdx.x] = s; rs2[threadIdx.x] = s2;
    __syncthreads();
    for (int off = 256; off > 0; off >>= 1) {
        if (threadIdx.x < off) {
            rs [threadIdx.x] += rs [threadIdx.x + off];
            rs2[threadIdx.x] += rs2[threadIdx.x + off];
        }
        __syncthreads();
    }
    if (threadIdx.x == 0) {
        const float invN = 1.f / (float)(CPG * HWC);
        float mean = rs[0] * invN;
        float var  = rs2[0] * invN - mean * mean;
        g_stats[bg * 2 + 0] = mean;
        g_stats[bg * 2 + 1] = rsqrtf(var + 1e-6f);
    }
}

// ---------------------------------------------------------------------------
// K2: fold GroupNorm affine into the QKV conv weights (per batch).
//   xn = x*sc + sh,  sc = rstd*gn_w[c],  sh = gn_b[c] - mean*sc
//   W'[o,c]  = W[o,c]*sc[c]
//   b'[o]    = b[o] + sum_c W[o,c]*sh[c]
// ---------------------------------------------------------------------------
__global__ __launch_bounds__(256) void prep_weights_kernel(
    const float* __restrict__ q_w, const float* __restrict__ q_b,
    const float* __restrict__ k_w, const float* __restrict__ k_b,
    const float* __restrict__ v_w, const float* __restrict__ v_b,
    const float* __restrict__ gn_w, const float* __restrict__ gn_b)
{
    int m = blockIdx.x;            // 0..767 (q:0-255, k:256-511, v:512-767)
    int b = blockIdx.y;
    int t = m >> 8, o = m & 255;
    const float* W; const float* Bv;
    if      (t == 0) { W = q_w; Bv = q_b; }
    else if (t == 1) { W = k_w; Bv = k_b; }
    else             { W = v_w; Bv = v_b; }

    int c = threadIdx.x;
    int g = c >> 3;
    float mean = g_stats[(b * NGRP + g) * 2 + 0];
    float rstd = g_stats[(b * NGRP + g) * 2 + 1];
    float sc = rstd * gn_w[c];
    float sh = gn_b[c] - mean * sc;
    float wv = W[o * 256 + c];
    g_wadj[((size_t)b * 768 + m) * 256 + c] = wv * sc;

    __shared__ float red[256];
    red[c] = wv * sh;
    __syncthreads();
    for (int off = 128; off > 0; off >>= 1) {
        if (c < off) red[c] += red[c + off];
        __syncthreads();
    }
    if (c == 0) g_badj[(size_t)b * 768 + m] = Bv[o] + red[0];
}

// ---------------------------------------------------------------------------
// K3/K5: fp32 SIMT GEMM, 128x128 block tile, K-tile 16, 8x8 microtiles,
// double-buffered smem with register prefetch.
//   out[b][m][n] = sum_k A[b][m][k] * X[b][k][n] + bias[b][m]
// X has row stride HWC (positions contiguous). Optional fused residual+scale.
// All dims divide exactly -> no bounds checks.
// ---------------------------------------------------------------------------
template <bool RES>
__global__ __launch_bounds__(256, 1) void gemm128_kernel(
    const float* __restrict__ A, long long Abs,
    const float* __restrict__ bias, int biasBs,
    const float* __restrict__ X, long long Xbs,
    float* __restrict__ out, long long Obs,
    const float* __restrict__ res, float scale)
{
    const int b = blockIdx.z;
    const float* Ab    = A    + (size_t)b * Abs;
    const float* Xb    = X    + (size_t)b * Xbs;
    float*       Ob    = out  + (size_t)b * Obs;
    const float* biasb = bias + (size_t)b * biasBs;
    const float* rb    = RES ? (res + (size_t)b * Obs) : nullptr;

    const int m0 = blockIdx.x * 128;
    const int n0 = blockIdx.y * 128;

    __shared__ float As[2][16][128];   // transposed: [k][m]
    __shared__ float Bs[2][16][128];   // [k][n]

    const int tid = threadIdx.x;
    const int tx = tid & 15, ty = tid >> 4;

    float acc[8][8];
#pragma unroll
    for (int i = 0; i < 8; i++)
#pragma unroll
        for (int j = 0; j < 8; j++) acc[i][j] = 0.f;

    // global-load assignments (2 float4 each for A and B per thread)
    const int v0 = tid * 2, v1 = tid * 2 + 1;
    const int arow0 = v0 >> 2, akc0 = (v0 & 3) << 2;
    const int arow1 = v1 >> 2, akc1 = (v1 & 3) << 2;
    const int bk0 = v0 >> 5, bnc0 = (v0 & 31) << 2;
    const int bk1 = v1 >> 5, bnc1 = (v1 & 31) << 2;

    float4 a0, a1, b0v, b1v;
    // prologue: tile 0
    {
        const int k0 = 0;
        a0  = *(const float4*)(Ab + (size_t)(m0 + arow0) * 256 + k0 + akc0);
        a1  = *(const float4*)(Ab + (size_t)(m0 + arow1) * 256 + k0 + akc1);
        b0v = *(const float4*)(Xb + (size_t)(k0 + bk0) * HWC + n0 + bnc0);
        b1v = *(const float4*)(Xb + (size_t)(k0 + bk1) * HWC + n0 + bnc1);
        As[0][akc0 + 0][arow0] = a0.x; As[0][akc0 + 1][arow0] = a0.y;
        As[0][akc0 + 2][arow0] = a0.z; As[0][akc0 + 3][arow0] = a0.w;
        As[0][akc1 + 0][arow1] = a1.x; As[0][akc1 + 1][arow1] = a1.y;
        As[0][akc1 + 2][arow1] = a1.z; As[0][akc1 + 3][arow1] = a1.w;
        *(float4*)&Bs[0][bk0][bnc0] = b0v;
        *(float4*)&Bs[0][bk1][bnc1] = b1v;
    }
    __syncthreads();

    int buf = 0;
    for (int kt = 0; kt < 16; kt++) {
        if (kt < 15) {
            const int k0 = (kt + 1) * 16;
            a0  = *(const float4*)(Ab + (size_t)(m0 + arow0) * 256 + k0 + akc0);
            a1  = *(const float4*)(Ab + (size_t)(m0 + arow1) * 256 + k0 + akc1);
            b0v = *(const float4*)(Xb + (size_t)(k0 + bk0) * HWC + n0 + bnc0);
            b1v = *(const float4*)(Xb + (size_t)(k0 + bk1) * HWC + n0 + bnc1);
        }
        const float* Asb = &As[buf][0][0];
        const float* Bsb = &Bs[buf][0][0];
#pragma unroll
        for (int kk = 0; kk < 16; kk++) {
            float af[8], bf[8];
            *(float4*)(af + 0) = *(const float4*)(Asb + kk * 128 + ty * 8);
            *(float4*)(af + 4) = *(const float4*)(Asb + kk * 128 + ty * 8 + 4);
            *(float4*)(bf + 0) = *(const float4*)(Bsb + kk * 128 + tx * 8);
            *(float4*)(bf + 4) = *(const float4*)(Bsb + kk * 128 + tx * 8 + 4);
#pragma unroll
            for (int i = 0; i < 8; i++)
#pragma unroll
                for (int j = 0; j < 8; j++)
                    acc[i][j] = fmaf(af[i], bf[j], acc[i][j]);
        }
        if (kt < 15) {
            int nb = buf ^ 1;
            As[nb][akc0 + 0][arow0] = a0.x; As[nb][akc0 + 1][arow0] = a0.y;
            As[nb][akc0 + 2][arow0] = a0.z; As[nb][akc0 + 3][arow0] = a0.w;
            As[nb][akc1 + 0][arow1] = a1.x; As[nb][akc1 + 1][arow1] = a1.y;
            As[nb][akc1 + 2][arow1] = a1.z; As[nb][akc1 + 3][arow1] = a1.w;
            *(float4*)&Bs[nb][bk0][bnc0] = b0v;
            *(float4*)&Bs[nb][bk1][bnc1] = b1v;
            __syncthreads();
            buf = nb;
        }
    }

    // epilogue
#pragma unroll
    for (int i = 0; i < 8; i++) {
        const int m = m0 + ty * 8 + i;
        const float bv = biasb[m];
        const size_t off = (size_t)m * HWC + n0 + tx * 8;
#pragma unroll
        for (int j = 0; j < 8; j += 4) {
            float4 r;
            r.x = acc[i][j + 0] + bv;
            r.y = acc[i][j + 1] + bv;
            r.z = acc[i][j + 2] + bv;
            r.w = acc[i][j + 3] + bv;
            if (RES) {
                float4 rv = *(const float4*)(rb + off + j);
                r.x = (r.x + rv.x) * scale;
                r.y = (r.y + rv.y) * scale;
                r.z = (r.z + rv.z) * scale;
                r.w = (r.w + rv.w) * scale;
            }
            *(float4*)(Ob + off + j) = r;
        }
    }
}

// ---------------------------------------------------------------------------
// K4: windowed MHA. One 64-thread block per (b, head, window).
// thread i owns query token i (8x8 window, token = (h%8)*8 + (w%8)).
// K/V staged in smem (padded stride 36 floats -> 16B-aligned rows),
// scores in smem (stride 65 -> conflict-free).
// ---------------------------------------------------------------------------
__global__ __launch_bounds__(64) void attn_kernel()
{
    const int win = blockIdx.x;            // 0..1023 = wy*32 + wx
    const int nh  = blockIdx.y;
    const int b   = blockIdx.z;
    const int wy = win >> 5, wx = win & 31;
    const int h0 = wy * 8, w0 = wx * 8;
    const int i = threadIdx.x;             // token index 0..63
    const size_t posi = (size_t)(h0 + (i >> 3)) * 256 + (w0 + (i & 7));

    const size_t base = ((size_t)b * 768 + nh * HD) * HWC;   // q channel base

    __shared__ float Ksh[64 * 36];
    __shared__ float Vsh[64 * 36];
    __shared__ float Ssh[64 * 65];

    // stage K, V tiles (64 tokens x 32 dims each)
    for (int idx = i; idx < 2048; idx += 64) {
        const int d = idx >> 6, j = idx & 63;
        const size_t p = (size_t)(h0 + (j >> 3)) * 256 + (w0 + (j & 7));
        Ksh[j * 36 + d] = g_qkv[base + (size_t)(256 + d) * HWC + p];
        Vsh[j * 36 + d] = g_qkv[base + (size_t)(512 + d) * HWC + p];
    }

    float qreg[32];
#pragma unroll
    for (int d = 0; d < 32; d++)
        qreg[d] = g_qkv[base + (size_t)d * HWC + posi];
    __syncthreads();

    // S = scale * q . K^T, track row max
    const float scale = 0.17677669529663687f;   // 32^-0.5
    float mx = -1e30f;
#pragma unroll 4
    for (int j = 0; j < 64; j++) {
        const float4* kr = (const float4*)(Ksh + j * 36);
        float s = 0.f;
#pragma unroll
        for (int dd = 0; dd < 8; dd++) {
            float4 kv = kr[dd];
            s = fmaf(qreg[dd * 4 + 0], kv.x, s);
            s = fmaf(qreg[dd * 4 + 1], kv.y, s);
            s = fmaf(qreg[dd * 4 + 2], kv.z, s);
            s = fmaf(qreg[dd * 4 + 3], kv.w, s);
        }
        s *= scale;
        Ssh[i * 65 + j] = s;
        mx = fmaxf(mx, s);
    }

    // softmax numerator + sum
    float sum = 0.f;
#pragma unroll 8
    for (int j = 0; j < 64; j++) {
        float p = __expf(Ssh[i * 65 + j] - mx);
        Ssh[i * 65 + j] = p;
        sum += p;
    }
    const float inv = 1.f / sum;

    // O = P @ V
    float o[32];
#pragma unroll
    for (int d = 0; d < 32; d++) o[d] = 0.f;
#pragma unroll 4
    for (int j = 0; j < 64; j++) {
        const float p = Ssh[i * 65 + j];
        const float4* vr = (const float4*)(Vsh + j * 36);
#pragma unroll
        for (int dd = 0; dd < 8; dd++) {
            float4 vv = vr[dd];
            o[dd * 4 + 0] = fmaf(p, vv.x, o[dd * 4 + 0]);
            o[dd * 4 + 1] = fmaf(p, vv.y, o[dd * 4 + 1]);
            o[dd * 4 + 2] = fmaf(p, vv.z, o[dd * 4 + 2]);
            o[dd * 4 + 3] = fmaf(p, vv.w, o[dd * 4 + 3]);
        }
    }

    const size_t obase = ((size_t)b * 256 + nh * HD) * HWC + posi;
#pragma unroll
    for (int d = 0; d < 32; d++)
        g_attn[obase + (size_t)d * HWC] = o[d] * inv;
}

// ---------------------------------------------------------------------------
// Launch
// ---------------------------------------------------------------------------
extern "C" void kernel_launch(void* const* d_in, const int* in_sizes, int n_in,
                              void* d_out, int out_size)
{
    const float* q    = (const float*)d_in[0];
    const float* gn_w = (const float*)d_in[1];
    const float* gn_b = (const float*)d_in[2];
    const float* q_w  = (const float*)d_in[3];
    const float* q_b  = (const float*)d_in[4];
    const float* k_w  = (const float*)d_in[5];
    const float* k_b  = (const float*)d_in[6];
    const float* v_w  = (const float*)d_in[7];
    const float* v_b  = (const float*)d_in[8];
    const float* o_w  = (const float*)d_in[9];
    const float* o_b  = (const float*)d_in[10];
    float* out = (float*)d_out;

    float *p_wadj, *p_badj, *p_qkv, *p_attn;
    cudaGetSymbolAddress((void**)&p_wadj, g_wadj);
    cudaGetSymbolAddress((void**)&p_badj, g_badj);
    cudaGetSymbolAddress((void**)&p_qkv,  g_qkv);
    cudaGetSymbolAddress((void**)&p_attn, g_attn);

    // 1. GroupNorm stats
    gn_stats_kernel<<<NBAT * NGRP, 512>>>(q);

    // 2. Fold GN into QKV weights/biases
    prep_weights_kernel<<<dim3(768, NBAT), 256>>>(q_w, q_b, k_w, k_b, v_w, v_b, gn_w, gn_b);

    // 3. Fused (GN + QKV projection): [768 x 256] @ [256 x 65536] per batch
    gemm128_kernel<false><<<dim3(6, 512, NBAT), 256>>>(
        p_wadj, 768LL * 256,
        p_badj, 768,
        q, (long long)CCH * HWC,
        p_qkv, 768LL * HWC,
        nullptr, 1.0f);

    // 4. Windowed attention
    attn_kernel<<<dim3(1024, NHEAD, NBAT), 64>>>();

    // 5. Output projection + residual + 2^-0.5 scale
    gemm128_kernel<true><<<dim3(2, 512, NBAT), 256>>>(
        o_w, 0,
        o_b, 0,
        p_attn, (long long)CCH * HWC,
        out, (long long)CCH * HWC,
        q, 0.70710678118654752f);
}

// round 5
// speedup vs baseline: 1.6556x; 1.6556x over previous
#include <cuda_runtime.h>
#include <cstddef>

// Problem constants
#define HWC   65536          // H*W = 256*256
#define CCH   256            // channels
#define NBAT  4
#define NHEAD 8
#define HD    32
#define NGRP  32
#define CPG   8              // channels per group

// ---------------------------------------------------------------------------
// f32x2 packed-math helpers (sm_100+): FFMA2 = 2 fp32 FMAs per instruction.
// ---------------------------------------------------------------------------
__device__ __forceinline__ unsigned long long pk2(float x, float y) {
    unsigned long long r;
    asm("mov.b64 %0, {%1, %2};" : "=l"(r) : "f"(x), "f"(y));
    return r;
}
__device__ __forceinline__ unsigned long long dup2(float x) {
    unsigned long long r;
    asm("mov.b64 %0, {%1, %1};" : "=l"(r) : "f"(x));
    return r;
}
__device__ __forceinline__ void unpk2(unsigned long long v, float& x, float& y) {
    asm("mov.b64 {%0, %1}, %2;" : "=f"(x), "=f"(y) : "l"(v));
}
__device__ __forceinline__ unsigned long long fma2(
    unsigned long long a, unsigned long long b, unsigned long long c) {
    unsigned long long d;
    asm("fma.rn.f32x2 %0, %1, %2, %3;" : "=l"(d) : "l"(a), "l"(b), "l"(c));
    return d;
}

// ---------------------------------------------------------------------------
// Scratch (static device globals — no allocation at kernel_launch time)
// ---------------------------------------------------------------------------
__device__ float g_stats[NBAT * NGRP * 2];          // mean, rstd per (b,g)
__device__ float g_wadj [NBAT * 768 * 256];         // GN-folded QKV weights
__device__ float g_badj [NBAT * 768];               // GN-folded QKV biases
__device__ float g_qkv  [(size_t)NBAT * 768 * HWC]; // q/k/v stacked, [b][768][HW]
__device__ float g_attn [(size_t)NBAT * 256 * HWC]; // attention output [b][C][HW]

// ---------------------------------------------------------------------------
// K1: GroupNorm statistics. One block per (b,g); group channels contiguous.
// ---------------------------------------------------------------------------
__global__ __launch_bounds__(512) void gn_stats_kernel(const float* __restrict__ q)
{
    int bg = blockIdx.x;                                  // 0..127
    const float4* base = (const float4*)(q + (size_t)bg * CPG * HWC);
    float s = 0.f, s2 = 0.f;
    for (int i = threadIdx.x; i < (CPG * HWC) / 4; i += 512) {
        float4 v = base[i];
        s  += v.x + v.y + v.z + v.w;
        s2 += v.x*v.x + v.y*v.y + v.z*v.z + v.w*v.w;
    }
    __shared__ float rs[512], rs2[512];
    rs[threadIdx.x] = s; rs2[threadIdx.x] = s2;
    __syncthreads();
    for (int off = 256; off > 0; off >>= 1) {
        if (threadIdx.x < off) {
            rs [threadIdx.x] += rs [threadIdx.x + off];
            rs2[threadIdx.x] += rs2[threadIdx.x + off];
        }
        __syncthreads();
    }
    if (threadIdx.x == 0) {
        const float invN = 1.f / (float)(CPG * HWC);
        float mean = rs[0] * invN;
        float var  = rs2[0] * invN - mean * mean;
        g_stats[bg * 2 + 0] = mean;
        g_stats[bg * 2 + 1] = rsqrtf(var + 1e-6f);
    }
}

// ---------------------------------------------------------------------------
// K2: fold GroupNorm affine into the QKV conv weights (per batch).
// ---------------------------------------------------------------------------
__global__ __launch_bounds__(256) void prep_weights_kernel(
    const float* __restrict__ q_w, const float* __restrict__ q_b,
    const float* __restrict__ k_w, const float* __restrict__ k_b,
    const float* __restrict__ v_w, const float* __restrict__ v_b,
    const float* __restrict__ gn_w, const float* __restrict__ gn_b)
{
    int m = blockIdx.x;            // 0..767 (q:0-255, k:256-511, v:512-767)
    int b = blockIdx.y;
    int t = m >> 8, o = m & 255;
    const float* W; const float* Bv;
    if      (t == 0) { W = q_w; Bv = q_b; }
    else if (t == 1) { W = k_w; Bv = k_b; }
    else             { W = v_w; Bv = v_b; }

    int c = threadIdx.x;
    int g = c >> 3;
    float mean = g_stats[(b * NGRP + g) * 2 + 0];
    float rstd = g_stats[(b * NGRP + g) * 2 + 1];
    float sc = rstd * gn_w[c];
    float sh = gn_b[c] - mean * sc;
    float wv = W[o * 256 + c];
    g_wadj[((size_t)b * 768 + m) * 256 + c] = wv * sc;

    __shared__ float red[256];
    red[c] = wv * sh;
    __syncthreads();
    for (int off = 128; off > 0; off >>= 1) {
        if (c < off) red[c] += red[c + off];
        __syncthreads();
    }
    if (c == 0) g_badj[(size_t)b * 768 + m] = Bv[o] + red[0];
}

// ---------------------------------------------------------------------------
// K3/K5: fp32 GEMM with FFMA2 microkernel. 128x128 block tile, K-tile 16,
// 8x8 microtiles held as 8x4 f32x2 pairs, double-buffered smem.
//   out[b][m][n] = sum_k A[b][m][k] * X[b][k][n] + bias[b][m]
// ---------------------------------------------------------------------------
template <bool RES>
__global__ __launch_bounds__(256, 1) void gemm128_kernel(
    const float* __restrict__ A, long long Abs,
    const float* __restrict__ bias, int biasBs,
    const float* __restrict__ X, long long Xbs,
    float* __restrict__ out, long long Obs,
    const float* __restrict__ res, float scale)
{
    const int b = blockIdx.z;
    const float* Ab    = A    + (size_t)b * Abs;
    const float* Xb    = X    + (size_t)b * Xbs;
    float*       Ob    = out  + (size_t)b * Obs;
    const float* biasb = bias + (size_t)b * biasBs;
    const float* rb    = RES ? (res + (size_t)b * Obs) : nullptr;

    const int m0 = blockIdx.x * 128;
    const int n0 = blockIdx.y * 128;

    __shared__ float As[2][16][128];   // transposed: [k][m]
    __shared__ float Bs[2][16][128];   // [k][n]

    const int tid = threadIdx.x;
    const int tx = tid & 15, ty = tid >> 4;

    unsigned long long acc2[8][4];     // [i][j-pair]
#pragma unroll
    for (int i = 0; i < 8; i++)
#pragma unroll
        for (int j = 0; j < 4; j++) acc2[i][j] = 0ull;

    // global-load assignments (2 float4 each for A and B per thread)
    const int v0 = tid * 2, v1 = tid * 2 + 1;
    const int arow0 = v0 >> 2, akc0 = (v0 & 3) << 2;
    const int arow1 = v1 >> 2, akc1 = (v1 & 3) << 2;
    const int bk0 = v0 >> 5, bnc0 = (v0 & 31) << 2;
    const int bk1 = v1 >> 5, bnc1 = (v1 & 31) << 2;

    float4 a0, a1, b0v, b1v;
    // prologue: tile 0
    {
        const int k0 = 0;
        a0  = *(const float4*)(Ab + (size_t)(m0 + arow0) * 256 + k0 + akc0);
        a1  = *(const float4*)(Ab + (size_t)(m0 + arow1) * 256 + k0 + akc1);
        b0v = *(const float4*)(Xb + (size_t)(k0 + bk0) * HWC + n0 + bnc0);
        b1v = *(const float4*)(Xb + (size_t)(k0 + bk1) * HWC + n0 + bnc1);
        As[0][akc0 + 0][arow0] = a0.x; As[0][akc0 + 1][arow0] = a0.y;
        As[0][akc0 + 2][arow0] = a0.z; As[0][akc0 + 3][arow0] = a0.w;
        As[0][akc1 + 0][arow1] = a1.x; As[0][akc1 + 1][arow1] = a1.y;
        As[0][akc1 + 2][arow1] = a1.z; As[0][akc1 + 3][arow1] = a1.w;
        *(float4*)&Bs[0][bk0][bnc0] = b0v;
        *(float4*)&Bs[0][bk1][bnc1] = b1v;
    }
    __syncthreads();

    int buf = 0;
    for (int kt = 0; kt < 16; kt++) {
        if (kt < 15) {
            const int k0 = (kt + 1) * 16;
            a0  = *(const float4*)(Ab + (size_t)(m0 + arow0) * 256 + k0 + akc0);
            a1  = *(const float4*)(Ab + (size_t)(m0 + arow1) * 256 + k0 + akc1);
            b0v = *(const float4*)(Xb + (size_t)(k0 + bk0) * HWC + n0 + bnc0);
            b1v = *(const float4*)(Xb + (size_t)(k0 + bk1) * HWC + n0 + bnc1);
        }
        const float* Asb = &As[buf][0][0];
        const float* Bsb = &Bs[buf][0][0];
#pragma unroll
        for (int kk = 0; kk < 16; kk++) {
            float af[8];
            *(float4*)(af + 0) = *(const float4*)(Asb + kk * 128 + ty * 8);
            *(float4*)(af + 4) = *(const float4*)(Asb + kk * 128 + ty * 8 + 4);
            const ulonglong2* bp = (const ulonglong2*)(Bsb + kk * 128 + tx * 8);
            ulonglong2 bq0 = bp[0], bq1 = bp[1];
            unsigned long long b2[4];
            b2[0] = bq0.x; b2[1] = bq0.y; b2[2] = bq1.x; b2[3] = bq1.y;
            unsigned long long ad[8];
#pragma unroll
            for (int i = 0; i < 8; i++) ad[i] = dup2(af[i]);
#pragma unroll
            for (int i = 0; i < 8; i++)
#pragma unroll
                for (int j = 0; j < 4; j++)
                    acc2[i][j] = fma2(ad[i], b2[j], acc2[i][j]);
        }
        if (kt < 15) {
            int nb = buf ^ 1;
            As[nb][akc0 + 0][arow0] = a0.x; As[nb][akc0 + 1][arow0] = a0.y;
            As[nb][akc0 + 2][arow0] = a0.z; As[nb][akc0 + 3][arow0] = a0.w;
            As[nb][akc1 + 0][arow1] = a1.x; As[nb][akc1 + 1][arow1] = a1.y;
            As[nb][akc1 + 2][arow1] = a1.z; As[nb][akc1 + 3][arow1] = a1.w;
            *(float4*)&Bs[nb][bk0][bnc0] = b0v;
            *(float4*)&Bs[nb][bk1][bnc1] = b1v;
            __syncthreads();
            buf = nb;
        }
    }

    // epilogue
#pragma unroll
    for (int i = 0; i < 8; i++) {
        const int m = m0 + ty * 8 + i;
        const float bv = biasb[m];
        const size_t off = (size_t)m * HWC + n0 + tx * 8;
        float vo[8];
#pragma unroll
        for (int j = 0; j < 4; j++) unpk2(acc2[i][j], vo[2 * j], vo[2 * j + 1]);
#pragma unroll
        for (int j = 0; j < 8; j += 4) {
            float4 r;
            r.x = vo[j + 0] + bv;
            r.y = vo[j + 1] + bv;
            r.z = vo[j + 2] + bv;
            r.w = vo[j + 3] + bv;
            if (RES) {
                float4 rv = *(const float4*)(rb + off + j);
                r.x = (r.x + rv.x) * scale;
                r.y = (r.y + rv.y) * scale;
                r.z = (r.z + rv.z) * scale;
                r.w = (r.w + rv.w) * scale;
            }
            *(float4*)(Ob + off + j) = r;
        }
    }
}

// ---------------------------------------------------------------------------
// K4: windowed MHA, single fused pass with FFMA2.
// One 64-thread block per (b, head, window); thread i owns query token i.
// No score buffer, no max-subtraction (scores bounded |s| << 80, exp is safe
// in fp32 and mathematically identical to max-shifted softmax).
// smem = K + V tiles only (18 KB) -> ~3x the old occupancy.
// ---------------------------------------------------------------------------
__global__ __launch_bounds__(64, 10) void attn_kernel()
{
    const int win = blockIdx.x;            // 0..1023 = wy*32 + wx
    const int nh  = blockIdx.y;
    const int b   = blockIdx.z;
    const int wy = win >> 5, wx = win & 31;
    const int h0 = wy * 8, w0 = wx * 8;
    const int i = threadIdx.x;             // token index 0..63
    const size_t posi = (size_t)(h0 + (i >> 3)) * 256 + (w0 + (i & 7));

    const size_t base = ((size_t)b * 768 + nh * HD) * HWC;   // q channel base

    __shared__ float Ksh[64 * 36];   // row stride 144B (16B aligned)
    __shared__ float Vsh[64 * 36];

    // stage K, V tiles (64 tokens x 32 dims each)
    for (int idx = i; idx < 2048; idx += 64) {
        const int d = idx >> 6, j = idx & 63;
        const size_t p = (size_t)(h0 + (j >> 3)) * 256 + (w0 + (j & 7));
        Ksh[j * 36 + d] = g_qkv[base + (size_t)(256 + d) * HWC + p];
        Vsh[j * 36 + d] = g_qkv[base + (size_t)(512 + d) * HWC + p];
    }

    // load q for this token, pre-scaled, packed into f32x2 pairs
    const float scale = 0.17677669529663687f;   // 32^-0.5
    unsigned long long q2[16];
#pragma unroll
    for (int dd = 0; dd < 16; dd++) {
        float a = g_qkv[base + (size_t)(2 * dd)     * HWC + posi] * scale;
        float c = g_qkv[base + (size_t)(2 * dd + 1) * HWC + posi] * scale;
        q2[dd] = pk2(a, c);
    }
    __syncthreads();

    unsigned long long o2[16];
#pragma unroll
    for (int dd = 0; dd < 16; dd++) o2[dd] = 0ull;
    float sum = 0.f;

#pragma unroll 2
    for (int j = 0; j < 64; j++) {
        const ulonglong2* kr = (const ulonglong2*)(Ksh + j * 36);
        unsigned long long s2 = 0ull;
#pragma unroll
        for (int t = 0; t < 8; t++) {
            ulonglong2 kv = kr[t];
            s2 = fma2(q2[2 * t], kv.x, s2);
            s2 = fma2(q2[2 * t + 1], kv.y, s2);
        }
        float slo, shi;
        unpk2(s2, slo, shi);
        const float p = __expf(slo + shi);
        sum += p;
        const unsigned long long pd = dup2(p);
        const ulonglong2* vr = (const ulonglong2*)(Vsh + j * 36);
#pragma unroll
        for (int t = 0; t < 8; t++) {
            ulonglong2 vv = vr[t];
            o2[2 * t]     = fma2(pd, vv.x, o2[2 * t]);
            o2[2 * t + 1] = fma2(pd, vv.y, o2[2 * t + 1]);
        }
    }

    const float inv = 1.f / sum;
    const size_t obase = ((size_t)b * 256 + nh * HD) * HWC + posi;
#pragma unroll
    for (int dd = 0; dd < 16; dd++) {
        float lo, hi;
        unpk2(o2[dd], lo, hi);
        g_attn[obase + (size_t)(2 * dd)     * HWC] = lo * inv;
        g_attn[obase + (size_t)(2 * dd + 1) * HWC] = hi * inv;
    }
}

// ---------------------------------------------------------------------------
// Launch
// ---------------------------------------------------------------------------
extern "C" void kernel_launch(void* const* d_in, const int* in_sizes, int n_in,
                              void* d_out, int out_size)
{
    const float* q    = (const float*)d_in[0];
    const float* gn_w = (const float*)d_in[1];
    const float* gn_b = (const float*)d_in[2];
    const float* q_w  = (const float*)d_in[3];
    const float* q_b  = (const float*)d_in[4];
    const float* k_w  = (const float*)d_in[5];
    const float* k_b  = (const float*)d_in[6];
    const float* v_w  = (const float*)d_in[7];
    const float* v_b  = (const float*)d_in[8];
    const float* o_w  = (const float*)d_in[9];
    const float* o_b  = (const float*)d_in[10];
    float* out = (float*)d_out;

    float *p_wadj, *p_badj, *p_qkv, *p_attn;
    cudaGetSymbolAddress((void**)&p_wadj, g_wadj);
    cudaGetSymbolAddress((void**)&p_badj, g_badj);
    cudaGetSymbolAddress((void**)&p_qkv,  g_qkv);
    cudaGetSymbolAddress((void**)&p_attn, g_attn);

    // 1. GroupNorm stats
    gn_stats_kernel<<<NBAT * NGRP, 512>>>(q);

    // 2. Fold GN into QKV weights/biases
    prep_weights_kernel<<<dim3(768, NBAT), 256>>>(q_w, q_b, k_w, k_b, v_w, v_b, gn_w, gn_b);

    // 3. Fused (GN + QKV projection): [768 x 256] @ [256 x 65536] per batch
    gemm128_kernel<false><<<dim3(6, 512, NBAT), 256>>>(
        p_wadj, 768LL * 256,
        p_badj, 768,
        q, (long long)CCH * HWC,
        p_qkv, 768LL * HWC,
        nullptr, 1.0f);

    // 4. Windowed attention
    attn_kernel<<<dim3(1024, NHEAD, NBAT), 64>>>();

    // 5. Output projection + residual + 2^-0.5 scale
    gemm128_kernel<true><<<dim3(2, 512, NBAT), 256>>>(
        o_w, 0,
        o_b, 0,
        p_attn, (long long)CCH * HWC,
        out, (long long)CCH * HWC,
        q, 0.70710678118654752f);
}

// round 7
// speedup vs baseline: 3.9960x; 2.4137x over previous
#include <cuda_runtime.h>
#include <cuda_bf16.h>
#include <cstdint>
#include <cstddef>

// Problem constants
#define HWC   65536          // H*W = 256*256
#define CCH   256            // channels
#define NBAT  4
#define NHEAD 8
#define HD    32
#define NGRP  32
#define CPG   8              // channels per group

// ===========================================================================
// Helpers
// ===========================================================================
__device__ __forceinline__ uint32_t smem_u32(const void* p) {
    uint32_t a;
    asm("{ .reg .u64 t; cvta.to.shared.u64 t, %1; cvt.u32.u64 %0, t; }"
        : "=r"(a) : "l"(p));
    return a;
}
__device__ __forceinline__ void ldsm_x4(uint32_t* r, uint32_t addr) {
    asm volatile("ldmatrix.sync.aligned.m8n8.x4.shared.b16 {%0,%1,%2,%3}, [%4];"
        : "=r"(r[0]), "=r"(r[1]), "=r"(r[2]), "=r"(r[3]) : "r"(addr));
}
__device__ __forceinline__ void ldsm_x4t(uint32_t* r, uint32_t addr) {
    asm volatile("ldmatrix.sync.aligned.m8n8.x4.trans.shared.b16 {%0,%1,%2,%3}, [%4];"
        : "=r"(r[0]), "=r"(r[1]), "=r"(r[2]), "=r"(r[3]) : "r"(addr));
}
__device__ __forceinline__ void mma_bf16(float* c, const uint32_t* a, const uint32_t* b) {
    asm volatile("mma.sync.aligned.m16n8k16.row.col.f32.bf16.bf16.f32 "
        "{%0,%1,%2,%3}, {%4,%5,%6,%7}, {%8,%9}, {%0,%1,%2,%3};"
        : "+f"(c[0]), "+f"(c[1]), "+f"(c[2]), "+f"(c[3])
        : "r"(a[0]), "r"(a[1]), "r"(a[2]), "r"(a[3]), "r"(b[0]), "r"(b[1]));
}

// f32x2 packed-math helpers (attention)
__device__ __forceinline__ unsigned long long pk2(float x, float y) {
    unsigned long long r;
    asm("mov.b64 %0, {%1, %2};" : "=l"(r) : "f"(x), "f"(y));
    return r;
}
__device__ __forceinline__ unsigned long long dup2(float x) {
    unsigned long long r;
    asm("mov.b64 %0, {%1, %1};" : "=l"(r) : "f"(x));
    return r;
}
__device__ __forceinline__ void unpk2(unsigned long long v, float& x, float& y) {
    asm("mov.b64 {%0, %1}, %2;" : "=f"(x), "=f"(y) : "l"(v));
}
__device__ __forceinline__ unsigned long long fma2(
    unsigned long long a, unsigned long long b, unsigned long long c) {
    unsigned long long d;
    asm("fma.rn.f32x2 %0, %1, %2, %3;" : "=l"(d) : "l"(a), "l"(b), "l"(c));
    return d;
}

// ---------------------------------------------------------------------------
// Scratch
// ---------------------------------------------------------------------------
__device__ float g_stats[NBAT * NGRP * 2];                 // mean, rstd per (b,g)
__device__ __nv_bfloat16 g_wadjb[NBAT * 768 * 256];        // GN-folded QKV weights bf16 [b][m][k]
__device__ __nv_bfloat16 g_owb[256 * 256];                 // o_w bf16 [o][c]
__device__ float g_badj [NBAT * 768];                      // GN-folded QKV biases
__device__ float g_qkv  [(size_t)NBAT * 768 * HWC];        // q/k/v stacked, [b][768][HW]
__device__ float g_attn [(size_t)NBAT * 256 * HWC];        // attention output [b][C][HW]

// ---------------------------------------------------------------------------
// K1: GroupNorm statistics
// ---------------------------------------------------------------------------
__global__ __launch_bounds__(512) void gn_stats_kernel(const float* __restrict__ q)
{
    int bg = blockIdx.x;                                  // 0..127
    const float4* base = (const float4*)(q + (size_t)bg * CPG * HWC);
    float s = 0.f, s2 = 0.f;
    for (int i = threadIdx.x; i < (CPG * HWC) / 4; i += 512) {
        float4 v = base[i];
        s  += v.x + v.y + v.z + v.w;
        s2 += v.x*v.x + v.y*v.y + v.z*v.z + v.w*v.w;
    }
    __shared__ float rs[512], rs2[512];
    rs[threadIdx.x] = s; rs2[threadIdx.x] = s2;
    __syncthreads();
    for (int off = 256; off > 0; off >>= 1) {
        if (threadIdx.x < off) {
            rs [threadIdx.x] += rs [threadIdx.x + off];
            rs2[threadIdx.x] += rs2[threadIdx.x + off];
        }
        __syncthreads();
    }
    if (threadIdx.x == 0) {
        const float invN = 1.f / (float)(CPG * HWC);
        float mean = rs[0] * invN;
        float var  = rs2[0] * invN - mean * mean;
        g_stats[bg * 2 + 0] = mean;
        g_stats[bg * 2 + 1] = rsqrtf(var + 1e-6f);
    }
}

// ---------------------------------------------------------------------------
// K2: fold GroupNorm into QKV weights -> bf16 [b][m][k]. Attention scale
// (32^-0.5) folded into the k projection (weights and bias).
// ---------------------------------------------------------------------------
__global__ __launch_bounds__(256) void prep_weights_kernel(
    const float* __restrict__ q_w, const float* __restrict__ q_b,
    const float* __restrict__ k_w, const float* __restrict__ k_b,
    const float* __restrict__ v_w, const float* __restrict__ v_b,
    const float* __restrict__ gn_w, const float* __restrict__ gn_b)
{
    int m = blockIdx.x;            // 0..767 (q:0-255, k:256-511, v:512-767)
    int b = blockIdx.y;
    int t = m >> 8, o = m & 255;
    const float* W; const float* Bv;
    if      (t == 0) { W = q_w; Bv = q_b; }
    else if (t == 1) { W = k_w; Bv = k_b; }
    else             { W = v_w; Bv = v_b; }
    const float KS = (t == 1) ? 0.17677669529663687f : 1.0f;

    int c = threadIdx.x;
    int g = c >> 3;
    float mean = g_stats[(b * NGRP + g) * 2 + 0];
    float rstd = g_stats[(b * NGRP + g) * 2 + 1];
    float sc = rstd * gn_w[c];
    float sh = gn_b[c] - mean * sc;
    float wv = W[o * 256 + c];

    g_wadjb[((size_t)b * 768 + m) * 256 + c] = __float2bfloat16(wv * sc * KS);

    __shared__ float red[256];
    red[c] = wv * sh;
    __syncthreads();
    for (int off = 128; off > 0; off >>= 1) {
        if (c < off) red[c] += red[c + off];
        __syncthreads();
    }
    if (c == 0) g_badj[(size_t)b * 768 + m] = (Bv[o] + red[0]) * KS;
}

__global__ __launch_bounds__(256) void prep_ow_kernel(const float* __restrict__ ow)
{
    int o = blockIdx.x, c = threadIdx.x;
    g_owb[o * 256 + c] = __float2bfloat16(ow[o * 256 + c]);
}

// ---------------------------------------------------------------------------
// K3/K5: bf16 mma.sync GEMM. out[b][m][n] = sum_k A[m][k]*X[b][k][n] + bias.
// CTA: N-tile 128, K=256 resident.
//   Xs: [k=256][n=128] bf16, 256B rows, 16B-chunk XOR swizzle (chunk ^ (k&7)).
//   As: [m=128][k=256] bf16, 512B rows, chunk ^ (m&7). Restaged per m-tile.
// 8 warps, warp tile 32m x 64n, m16n8k16: A via ldmatrix.x4,
// B via ldmatrix.x4.trans directly from natural [k][n] layout.
// ---------------------------------------------------------------------------
#define SM_X   0
#define SM_A   65536
#define SM_TOT 131072

template <int MT, bool RES>
__global__ __launch_bounds__(256) void gemm_mma_kernel(
    const __nv_bfloat16* __restrict__ Abf, long long Abs,
    const float* __restrict__ bias, int biasBs,
    const float* __restrict__ X, long long Xbs,
    float* __restrict__ out, long long Obs,
    const float* __restrict__ res, float scale)
{
    extern __shared__ char smem[];
    const uint32_t sb = smem_u32(smem);
    const int tid = threadIdx.x, wid = tid >> 5, lane = tid & 31;
    const int b = blockIdx.y;
    const int n0 = blockIdx.x * 128;

    // ---- stage X: fp32 [k][n] -> bf16 swizzled [k][n] ----
    const float* Xb = X + (size_t)b * Xbs + n0;
#pragma unroll 4
    for (int it = 0; it < 32; it++) {
        int idx = tid + it * 256;             // 8192 float4s = 256k x 32 groups
        int k = idx >> 5, n4 = idx & 31;      // n = n4*4
        float4 v = *(const float4*)(Xb + (size_t)k * HWC + n4 * 4);
        __nv_bfloat162 p0 = __floats2bfloat162_rn(v.x, v.y);
        __nv_bfloat162 p1 = __floats2bfloat162_rn(v.z, v.w);
        uint2 u;
        u.x = *reinterpret_cast<uint32_t*>(&p0);
        u.y = *reinterpret_cast<uint32_t*>(&p1);
        int chunk = n4 >> 1, half = n4 & 1;
        *(uint2*)(smem + SM_X + k * 256 + (((chunk ^ (k & 7)) << 4) + half * 8)) = u;
    }

    // ---- per-lane ldmatrix address invariants ----
    const int wm = (wid & 3) * 32;            // warp m offset within 128
    const int wn = (wid >> 2) * 64;           // warp n offset within 128
    // A: lanes 0-15 rows m0-15 (asel=0 -> k-chunk lo), 16-31 same rows (chunk hi)
    const int arow = wm + (lane & 15);
    const int asel = lane >> 4;
    const int ar7  = arow & 7;
    const uint32_t aBase0 = sb + SM_A + (uint32_t)arow * 512;
    const uint32_t aBase1 = aBase0 + 16 * 512;
    // B (trans): g = lane>>3: g0: k0-7 chunk c, g1: k8-15 chunk c, g2: k0-7 c+1, g3: k8-15 c+1
    const int gg = lane >> 3, ll = lane & 7;
    const int kb = (gg & 1) * 8 + ll;         // k row within 16-step
    const int br7 = kb & 7;
    uint32_t bBase[4];
#pragma unroll
    for (int j = 0; j < 4; j++) {
        int cn = (wn >> 3) + j * 2 + (gg >> 1);   // 16B n-chunk index (0..15)
        bBase[j] = sb + SM_X + (uint32_t)kb * 256 + (uint32_t)((cn ^ br7) << 4);
    }

    const int er = lane >> 2, ec = (lane & 3) * 2;   // epilogue row/col within frag
    const __nv_bfloat16* Ab = Abf + (size_t)b * Abs;

    for (int mt = 0; mt < MT; mt++) {
        // ---- stage A tile [128][256] bf16 with swizzle ----
        const uint4* asrc = (const uint4*)(Ab + (size_t)mt * 32768);
#pragma unroll 4
        for (int i = tid; i < 4096; i += 256) {
            int row = i >> 5, ch = i & 31;
            uint4 v = asrc[i];
            *(uint4*)(smem + SM_A + row * 512 + ((ch ^ (row & 7)) << 4)) = v;
        }
        __syncthreads();

        float c[2][8][4];
#pragma unroll
        for (int mi = 0; mi < 2; mi++)
#pragma unroll
            for (int ni = 0; ni < 8; ni++)
#pragma unroll
                for (int t = 0; t < 4; t++) c[mi][ni][t] = 0.f;

#pragma unroll 4
        for (int ks = 0; ks < 16; ks++) {
            uint32_t a0[4], a1[4];
            const uint32_t aoff = (uint32_t)(((ks * 2 + asel) ^ ar7) << 4);
            ldsm_x4(a0, aBase0 + aoff);
            ldsm_x4(a1, aBase1 + aoff);
            uint32_t bf[8][2];
#pragma unroll
            for (int j = 0; j < 4; j++) {
                uint32_t r[4];
                ldsm_x4t(r, bBase[j] + (uint32_t)ks * 4096);
                bf[2 * j][0] = r[0];     bf[2 * j][1] = r[1];
                bf[2 * j + 1][0] = r[2]; bf[2 * j + 1][1] = r[3];
            }
#pragma unroll
            for (int ni = 0; ni < 8; ni++) {
                mma_bf16(c[0][ni], a0, bf[ni]);
                mma_bf16(c[1][ni], a1, bf[ni]);
            }
        }
        __syncthreads();   // all LDSM done; As may be overwritten next iter

        // ---- epilogue: bias (+ residual, scale), float2 stores ----
#pragma unroll
        for (int mi = 0; mi < 2; mi++) {
            const int m0g = mt * 128 + wm + mi * 16 + er;
            const float bv0 = bias[(size_t)b * biasBs + m0g];
            const float bv1 = bias[(size_t)b * biasBs + m0g + 8];
            float* o0 = out + (size_t)b * Obs + (size_t)m0g * HWC + n0 + wn + ec;
            float* o1 = o0 + 8 * HWC;
            const float* r0 = RES ? (res + (size_t)b * Obs + (size_t)m0g * HWC + n0 + wn + ec)
                                  : nullptr;
            const float* r1 = RES ? (r0 + 8 * HWC) : nullptr;
#pragma unroll
            for (int ni = 0; ni < 8; ni++) {
                float2 v0, v1;
                v0.x = c[mi][ni][0] + bv0; v0.y = c[mi][ni][1] + bv0;
                v1.x = c[mi][ni][2] + bv1; v1.y = c[mi][ni][3] + bv1;
                if (RES) {
                    float2 q0 = *(const float2*)(r0 + ni * 8);
                    float2 q1 = *(const float2*)(r1 + ni * 8);
                    v0.x = (v0.x + q0.x) * scale; v0.y = (v0.y + q0.y) * scale;
                    v1.x = (v1.x + q1.x) * scale; v1.y = (v1.y + q1.y) * scale;
                }
                *(float2*)(o0 + ni * 8) = v0;
                *(float2*)(o1 + ni * 8) = v1;
            }
        }
    }
}

// ---------------------------------------------------------------------------
// K4: windowed MHA, single fused pass with FFMA2. scale pre-folded into k.
// ---------------------------------------------------------------------------
__global__ __launch_bounds__(64, 10) void attn_kernel()
{
    const int win = blockIdx.x;            // 0..1023 = wy*32 + wx
    const int nh  = blockIdx.y;
    const int b   = blockIdx.z;
    const int wy = win >> 5, wx = win & 31;
    const int h0 = wy * 8, w0 = wx * 8;
    const int i = threadIdx.x;             // token index 0..63
    const size_t posi = (size_t)(h0 + (i >> 3)) * 256 + (w0 + (i & 7));

    const size_t base = ((size_t)b * 768 + nh * HD) * HWC;   // q channel base

    __shared__ float Ksh[64 * 36];
    __shared__ float Vsh[64 * 36];

    for (int idx = i; idx < 2048; idx += 64) {
        const int d = idx >> 6, j = idx & 63;
        const size_t p = (size_t)(h0 + (j >> 3)) * 256 + (w0 + (j & 7));
        Ksh[j * 36 + d] = g_qkv[base + (size_t)(256 + d) * HWC + p];
        Vsh[j * 36 + d] = g_qkv[base + (size_t)(512 + d) * HWC + p];
    }

    unsigned long long q2[16];
#pragma unroll
    for (int dd = 0; dd < 16; dd++) {
        float a = g_qkv[base + (size_t)(2 * dd)     * HWC + posi];
        float c = g_qkv[base + (size_t)(2 * dd + 1) * HWC + posi];
        q2[dd] = pk2(a, c);
    }
    __syncthreads();

    unsigned long long o2[16];
#pragma unroll
    for (int dd = 0; dd < 16; dd++) o2[dd] = 0ull;
    float sum = 0.f;

#pragma unroll 2
    for (int j = 0; j < 64; j++) {
        const ulonglong2* kr = (const ulonglong2*)(Ksh + j * 36);
        unsigned long long sa = 0ull, sb2 = 0ull;   // two dependent chains
#pragma unroll
        for (int t = 0; t < 8; t++) {
            ulonglong2 kv = kr[t];
            sa  = fma2(q2[2 * t],     kv.x, sa);
            sb2 = fma2(q2[2 * t + 1], kv.y, sb2);
        }
        float a0, a1, b0, b1;
        unpk2(sa, a0, a1); unpk2(sb2, b0, b1);
        const float p = __expf((a0 + a1) + (b0 + b1));
        sum += p;
        const unsigned long long pd = dup2(p);
        const ulonglong2* vr = (const ulonglong2*)(Vsh + j * 36);
#pragma unroll
        for (int t = 0; t < 8; t++) {
            ulonglong2 vv = vr[t];
            o2[2 * t]     = fma2(pd, vv.x, o2[2 * t]);
            o2[2 * t + 1] = fma2(pd, vv.y, o2[2 * t + 1]);
        }
    }

    const float inv = 1.f / sum;
    const size_t obase = ((size_t)b * 256 + nh * HD) * HWC + posi;
#pragma unroll
    for (int dd = 0; dd < 16; dd++) {
        float lo, hi;
        unpk2(o2[dd], lo, hi);
        g_attn[obase + (size_t)(2 * dd)     * HWC] = lo * inv;
        g_attn[obase + (size_t)(2 * dd + 1) * HWC] = hi * inv;
    }
}

// ---------------------------------------------------------------------------
// Launch
// ---------------------------------------------------------------------------
extern "C" void kernel_launch(void* const* d_in, const int* in_sizes, int n_in,
                              void* d_out, int out_size)
{
    const float* q    = (const float*)d_in[0];
    const float* gn_w = (const float*)d_in[1];
    const float* gn_b = (const float*)d_in[2];
    const float* q_w  = (const float*)d_in[3];
    const float* q_b  = (const float*)d_in[4];
    const float* k_w  = (const float*)d_in[5];
    const float* k_b  = (const float*)d_in[6];
    const float* v_w  = (const float*)d_in[7];
    const float* v_b  = (const float*)d_in[8];
    const float* o_w  = (const float*)d_in[9];
    const float* o_b  = (const float*)d_in[10];
    float* out = (float*)d_out;

    __nv_bfloat16 *p_wadjb, *p_owb;
    float *p_badj, *p_qkv, *p_attn;
    cudaGetSymbolAddress((void**)&p_wadjb, g_wadjb);
    cudaGetSymbolAddress((void**)&p_owb,   g_owb);
    cudaGetSymbolAddress((void**)&p_badj,  g_badj);
    cudaGetSymbolAddress((void**)&p_qkv,   g_qkv);
    cudaGetSymbolAddress((void**)&p_attn,  g_attn);

    cudaFuncSetAttribute(gemm_mma_kernel<6, false>,
                         cudaFuncAttributeMaxDynamicSharedMemorySize, SM_TOT);
    cudaFuncSetAttribute(gemm_mma_kernel<2, true>,
                         cudaFuncAttributeMaxDynamicSharedMemorySize, SM_TOT);

    // 1. GroupNorm stats
    gn_stats_kernel<<<NBAT * NGRP, 512>>>(q);

    // 2. Fold GN into QKV weights (bf16); o_w -> bf16
    prep_weights_kernel<<<dim3(768, NBAT), 256>>>(q_w, q_b, k_w, k_b, v_w, v_b, gn_w, gn_b);
    prep_ow_kernel<<<256, 256>>>(o_w);

    // 3. Fused (GN + QKV projection): [768 x 256] @ [256 x 65536] per batch
    gemm_mma_kernel<6, false><<<dim3(512, NBAT), 256, SM_TOT>>>(
        p_wadjb, 768LL * 256,
        p_badj, 768,
        q, (long long)CCH * HWC,
        p_qkv, 768LL * HWC,
        nullptr, 1.0f);

    // 4. Windowed attention
    attn_kernel<<<dim3(1024, NHEAD, NBAT), 64>>>();

    // 5. Output projection + residual + 2^-0.5 scale
    gemm_mma_kernel<2, true><<<dim3(512, NBAT), 256, SM_TOT>>>(
        p_owb, 0,
        o_b, 0,
        p_attn, (long long)CCH * HWC,
        out, (long long)CCH * HWC,
        q, 0.70710678118654752f);
}

// round 8
// speedup vs baseline: 7.3445x; 1.8379x over previous
#include <cuda_runtime.h>
#include <cuda_bf16.h>
#include <cstdint>
#include <cstddef>

// Problem constants
#define HWC   65536          // H*W = 256*256
#define CCH   256            // channels
#define NBAT  4
#define NHEAD 8
#define HD    32
#define NGRP  32
#define CPG   8              // channels per group

// ===========================================================================
// Helpers
// ===========================================================================
__device__ __forceinline__ uint32_t smem_u32(const void* p) {
    uint32_t a;
    asm("{ .reg .u64 t; cvta.to.shared.u64 t, %1; cvt.u32.u64 %0, t; }"
        : "=r"(a) : "l"(p));
    return a;
}
__device__ __forceinline__ void ldsm_x4(uint32_t* r, uint32_t addr) {
    asm volatile("ldmatrix.sync.aligned.m8n8.x4.shared.b16 {%0,%1,%2,%3}, [%4];"
        : "=r"(r[0]), "=r"(r[1]), "=r"(r[2]), "=r"(r[3]) : "r"(addr));
}
__device__ __forceinline__ void ldsm_x4t(uint32_t* r, uint32_t addr) {
    asm volatile("ldmatrix.sync.aligned.m8n8.x4.trans.shared.b16 {%0,%1,%2,%3}, [%4];"
        : "=r"(r[0]), "=r"(r[1]), "=r"(r[2]), "=r"(r[3]) : "r"(addr));
}
__device__ __forceinline__ void mma_bf16(float* c, const uint32_t* a, const uint32_t* b) {
    asm volatile("mma.sync.aligned.m16n8k16.row.col.f32.bf16.bf16.f32 "
        "{%0,%1,%2,%3}, {%4,%5,%6,%7}, {%8,%9}, {%0,%1,%2,%3};"
        : "+f"(c[0]), "+f"(c[1]), "+f"(c[2]), "+f"(c[3])
        : "r"(a[0]), "r"(a[1]), "r"(a[2]), "r"(a[3]), "r"(b[0]), "r"(b[1]));
}
__device__ __forceinline__ void cp16(uint32_t dst, const void* src) {
    asm volatile("cp.async.cg.shared.global [%0], [%1], 16;" :: "r"(dst), "l"(src));
}
#define CP_COMMIT() asm volatile("cp.async.commit_group;" ::: "memory")
#define CP_WAIT0()  asm volatile("cp.async.wait_group 0;" ::: "memory")

__device__ __forceinline__ void store2(float* p, float x, float y) {
    *(float2*)p = make_float2(x, y);
}
__device__ __forceinline__ void store2(__nv_bfloat16* p, float x, float y) {
    *(__nv_bfloat162*)p = __floats2bfloat162_rn(x, y);
}
__device__ __forceinline__ uint32_t pack_bf2(float x, float y) {
    __nv_bfloat162 h = __floats2bfloat162_rn(x, y);
    return *reinterpret_cast<uint32_t*>(&h);
}

// ---------------------------------------------------------------------------
// Scratch
// ---------------------------------------------------------------------------
__device__ float g_stats[NBAT * NGRP * 2];
__device__ __align__(16) __nv_bfloat16 g_wadjb[NBAT * 768 * 256];  // GN-folded QKV weights [b][m][k]
__device__ __align__(16) __nv_bfloat16 g_owb[256 * 256];           // o_w bf16 [o][c]
__device__ float g_badj[NBAT * 768];
__device__ __align__(16) __nv_bfloat16 g_qkv[(size_t)NBAT * 768 * HWC];  // [b][768][HW] bf16
__device__ __align__(16) __nv_bfloat16 g_attn[(size_t)NBAT * 256 * HWC]; // [b][C][HW] bf16

// ---------------------------------------------------------------------------
// K1: GroupNorm statistics
// ---------------------------------------------------------------------------
__global__ __launch_bounds__(512) void gn_stats_kernel(const float* __restrict__ q)
{
    int bg = blockIdx.x;
    const float4* base = (const float4*)(q + (size_t)bg * CPG * HWC);
    float s = 0.f, s2 = 0.f;
    for (int i = threadIdx.x; i < (CPG * HWC) / 4; i += 512) {
        float4 v = base[i];
        s  += v.x + v.y + v.z + v.w;
        s2 += v.x*v.x + v.y*v.y + v.z*v.z + v.w*v.w;
    }
    __shared__ float rs[512], rs2[512];
    rs[threadIdx.x] = s; rs2[threadIdx.x] = s2;
    __syncthreads();
    for (int off = 256; off > 0; off >>= 1) {
        if (threadIdx.x < off) {
            rs [threadIdx.x] += rs [threadIdx.x + off];
            rs2[threadIdx.x] += rs2[threadIdx.x + off];
        }
        __syncthreads();
    }
    if (threadIdx.x == 0) {
        const float invN = 1.f / (float)(CPG * HWC);
        float mean = rs[0] * invN;
        float var  = rs2[0] * invN - mean * mean;
        g_stats[bg * 2 + 0] = mean;
        g_stats[bg * 2 + 1] = rsqrtf(var + 1e-6f);
    }
}

// ---------------------------------------------------------------------------
// K2: fold GroupNorm into QKV weights -> bf16 [b][m][k]; 32^-0.5 folded into k.
// ---------------------------------------------------------------------------
__global__ __launch_bounds__(256) void prep_weights_kernel(
    const float* __restrict__ q_w, const float* __restrict__ q_b,
    const float* __restrict__ k_w, const float* __restrict__ k_b,
    const float* __restrict__ v_w, const float* __restrict__ v_b,
    const float* __restrict__ gn_w, const float* __restrict__ gn_b)
{
    int m = blockIdx.x;
    int b = blockIdx.y;
    int t = m >> 8, o = m & 255;
    const float* W; const float* Bv;
    if      (t == 0) { W = q_w; Bv = q_b; }
    else if (t == 1) { W = k_w; Bv = k_b; }
    else             { W = v_w; Bv = v_b; }
    const float KS = (t == 1) ? 0.17677669529663687f : 1.0f;

    int c = threadIdx.x;
    int g = c >> 3;
    float mean = g_stats[(b * NGRP + g) * 2 + 0];
    float rstd = g_stats[(b * NGRP + g) * 2 + 1];
    float sc = rstd * gn_w[c];
    float sh = gn_b[c] - mean * sc;
    float wv = W[o * 256 + c];

    g_wadjb[((size_t)b * 768 + m) * 256 + c] = __float2bfloat16(wv * sc * KS);

    __shared__ float red[256];
    red[c] = wv * sh;
    __syncthreads();
    for (int off = 128; off > 0; off >>= 1) {
        if (c < off) red[c] += red[c + off];
        __syncthreads();
    }
    if (c == 0) g_badj[(size_t)b * 768 + m] = (Bv[o] + red[0]) * KS;
}

__global__ __launch_bounds__(256) void prep_ow_kernel(const float* __restrict__ ow)
{
    int o = blockIdx.x, c = threadIdx.x;
    g_owb[o * 256 + c] = __float2bfloat16(ow[o * 256 + c]);
}

// ---------------------------------------------------------------------------
// K3/K5: bf16 mma.sync GEMM, cp.async double-buffered A tiles.
// out[b][m][n] = sum_k A[m][k]*X[b][k][n] + bias.
//   Xs: [k=256][n=128] bf16, 256B rows, 16B-chunk XOR swizzle (chunk ^ (k&7)).
//   As: [m=128][k=256] bf16, 512B rows, chunk ^ (m&7). Double buffered.
// ---------------------------------------------------------------------------
#define SM_X    0
#define SM_A    65536
#define SM_TOT  196608

// stage X tile: fp32 source (convert to bf16, manual stores)
__device__ __forceinline__ void stage_x(char* smem, const float* Xb, int tid)
{
#pragma unroll 4
    for (int it = 0; it < 32; it++) {
        int idx = tid + it * 256;
        int k = idx >> 5, n4 = idx & 31;
        float4 v = *(const float4*)(Xb + (size_t)k * HWC + n4 * 4);
        uint2 u;
        u.x = pack_bf2(v.x, v.y);
        u.y = pack_bf2(v.z, v.w);
        int chunk = n4 >> 1, half = n4 & 1;
        *(uint2*)(smem + SM_X + k * 256 + (((chunk ^ (k & 7)) << 4) + half * 8)) = u;
    }
}
// stage X tile: bf16 source (cp.async straight copies)
__device__ __forceinline__ void stage_x(char* smem, const __nv_bfloat16* Xb, int tid)
{
    const uint32_t sb = smem_u32(smem);
#pragma unroll 4
    for (int i = tid; i < 4096; i += 256) {
        int k = i >> 4, g = i & 15;
        cp16(sb + SM_X + k * 256 + ((g ^ (k & 7)) << 4),
             Xb + (size_t)k * HWC + g * 8);
    }
}

template <int MT, bool RES, typename TIN, typename TOUT>
__global__ __launch_bounds__(256) void gemm_mma_kernel(
    const __nv_bfloat16* __restrict__ Abf, long long Abs,
    const float* __restrict__ bias, int biasBs,
    const TIN* __restrict__ X, long long Xbs,
    TOUT* __restrict__ out, long long Obs,
    const float* __restrict__ res, float scale)
{
    extern __shared__ char smem[];
    const uint32_t sb = smem_u32(smem);
    const int tid = threadIdx.x, wid = tid >> 5, lane = tid & 31;
    const int b = blockIdx.y;
    const int n0 = blockIdx.x * 128;

    const __nv_bfloat16* Ab = Abf + (size_t)b * Abs;

    // ---- prologue: stage X + issue A tile 0 ----
    stage_x(smem, X + (size_t)b * Xbs + n0, tid);
    {
        const __nv_bfloat16* asrc = Ab;
#pragma unroll 4
        for (int i = tid; i < 4096; i += 256) {
            int row = i >> 5, ch = i & 31;
            cp16(sb + SM_A + row * 512 + ((ch ^ (row & 7)) << 4), asrc + i * 8);
        }
    }
    CP_COMMIT();

    // ---- per-lane ldmatrix invariants ----
    const int wm = (wid & 3) * 32;
    const int wn = (wid >> 2) * 64;
    const int arow = wm + (lane & 15);
    const int asel = lane >> 4;
    const int ar7  = arow & 7;
    const uint32_t aBase0 = sb + SM_A + (uint32_t)arow * 512;
    const uint32_t aBase1 = aBase0 + 16 * 512;
    const int gg = lane >> 3, ll = lane & 7;
    const int kb = (gg & 1) * 8 + ll;
    const int br7 = kb & 7;
    uint32_t bBase[4];
#pragma unroll
    for (int j = 0; j < 4; j++) {
        int cn = (wn >> 3) + j * 2 + (gg >> 1);
        bBase[j] = sb + SM_X + (uint32_t)kb * 256 + (uint32_t)((cn ^ br7) << 4);
    }
    const int er = lane >> 2, ec = (lane & 3) * 2;

    for (int mt = 0; mt < MT; mt++) {
        CP_WAIT0();
        __syncthreads();
        if (mt + 1 < MT) {
            const __nv_bfloat16* asrc = Ab + (size_t)(mt + 1) * 32768;
            const uint32_t abuf = SM_A + (uint32_t)((mt + 1) & 1) * 65536;
#pragma unroll 4
            for (int i = tid; i < 4096; i += 256) {
                int row = i >> 5, ch = i & 31;
                cp16(sb + abuf + row * 512 + ((ch ^ (row & 7)) << 4), asrc + i * 8);
            }
            CP_COMMIT();
        }
        const uint32_t abuf = (uint32_t)(mt & 1) * 65536;

        float c[2][8][4];
#pragma unroll
        for (int mi = 0; mi < 2; mi++)
#pragma unroll
            for (int ni = 0; ni < 8; ni++)
#pragma unroll
                for (int t = 0; t < 4; t++) c[mi][ni][t] = 0.f;

#pragma unroll 4
        for (int ks = 0; ks < 16; ks++) {
            uint32_t a0[4], a1[4];
            const uint32_t aoff = abuf + (uint32_t)(((ks * 2 + asel) ^ ar7) << 4);
            ldsm_x4(a0, aBase0 + aoff);
            ldsm_x4(a1, aBase1 + aoff);
            uint32_t bf[8][2];
#pragma unroll
            for (int j = 0; j < 4; j++) {
                uint32_t r[4];
                ldsm_x4t(r, bBase[j] + (uint32_t)ks * 4096);
                bf[2 * j][0] = r[0];     bf[2 * j][1] = r[1];
                bf[2 * j + 1][0] = r[2]; bf[2 * j + 1][1] = r[3];
            }
#pragma unroll
            for (int ni = 0; ni < 8; ni++) {
                mma_bf16(c[0][ni], a0, bf[ni]);
                mma_bf16(c[1][ni], a1, bf[ni]);
            }
        }

        // ---- epilogue ----
#pragma unroll
        for (int mi = 0; mi < 2; mi++) {
            const int m0g = mt * 128 + wm + mi * 16 + er;
            const float bv0 = bias[(size_t)b * biasBs + m0g];
            const float bv1 = bias[(size_t)b * biasBs + m0g + 8];
            TOUT* o0 = out + (size_t)b * Obs + (size_t)m0g * HWC + n0 + wn + ec;
            TOUT* o1 = o0 + 8 * HWC;
            const float* r0 = RES ? (res + (size_t)b * Obs + (size_t)m0g * HWC + n0 + wn + ec)
                                  : nullptr;
            const float* r1 = RES ? (r0 + 8 * HWC) : nullptr;
#pragma unroll
            for (int ni = 0; ni < 8; ni++) {
                float x0 = c[mi][ni][0] + bv0, y0 = c[mi][ni][1] + bv0;
                float x1 = c[mi][ni][2] + bv1, y1 = c[mi][ni][3] + bv1;
                if (RES) {
                    float2 q0 = *(const float2*)(r0 + ni * 8);
                    float2 q1 = *(const float2*)(r1 + ni * 8);
                    x0 = (x0 + q0.x) * scale; y0 = (y0 + q0.y) * scale;
                    x1 = (x1 + q1.x) * scale; y1 = (y1 + q1.y) * scale;
                }
                store2(o0 + ni * 8, x0, y0);
                store2(o1 + ni * 8, x1, y1);
            }
        }
    }
}

// ---------------------------------------------------------------------------
// K4: windowed MHA with mma.sync bf16.
// Block = 128 threads = 4 warps = 2 window-heads (2 warps each: query halves).
// Q/K/V all staged [dim(32)][token(64)] bf16, 128B rows, chunk^(d&7) swizzle.
//   Q a-frags : ldsm.x4.trans   K b-frags: ldsm.x4.trans   V b-frags: ldsm.x4
// No max-subtraction (scores tiny, validated R5-R7).
// ---------------------------------------------------------------------------
__global__ __launch_bounds__(128) void attn_mma_kernel(
    const __nv_bfloat16* __restrict__ qkv, __nv_bfloat16* __restrict__ attn)
{
    __shared__ __align__(16) char smem[24576];
    const int tid = threadIdx.x, wid = tid >> 5, lane = tid & 31;
    const int win = blockIdx.x, hp = blockIdx.y, b = blockIdx.z;
    const int wy = win >> 5, wx = win & 31;
    const int h0 = wy * 8, w0 = wx * 8;

    // ---- stage: [whl 2][tensor 3][d 32][8 x 16B chunks] ----
    {
        const size_t gbase = (size_t)b * 768 * HWC;
#pragma unroll
        for (int idx = tid; idx < 1536; idx += 128) {
            int tr = idx & 7, d = (idx >> 3) & 31, whl = (idx >> 8) & 1, t = idx >> 9;
            int ch = t * 256 + (hp * 2 + whl) * 32 + d;
            uint4 v = *(const uint4*)(qkv + gbase + (size_t)ch * HWC
                                      + (size_t)(h0 + tr) * 256 + w0);
            *(uint4*)(smem + whl * 12288 + t * 4096 + d * 128 + ((tr ^ (d & 7)) << 4)) = v;
        }
    }
    __syncthreads();

    const uint32_t sb = smem_u32(smem);
    const int whl = wid >> 1, wpair = wid & 1;
    const uint32_t Qs = sb + whl * 12288;
    const uint32_t Ks = Qs + 4096;
    const uint32_t Vs = Qs + 8192;
    const int mbase = wpair * 32;

    const int rlo = lane & 7, rsel = lane >> 4, csel = (lane >> 3) & 1;

    // ---- Q a-frags (resident): [mi][ks][4] ----
    uint32_t qa[2][2][4];
#pragma unroll
    for (int mi = 0; mi < 2; mi++)
#pragma unroll
        for (int ks = 0; ks < 2; ks++) {
            int rd = ks * 16 + rsel * 8 + rlo;
            int chunk = (mbase >> 3) + mi * 2 + csel;
            ldsm_x4t(qa[mi][ks], Qs + rd * 128 + ((chunk ^ (rd & 7)) << 4));
        }

    // ---- S = Q K^T ----
    float c[2][8][4];
#pragma unroll
    for (int mi = 0; mi < 2; mi++)
#pragma unroll
        for (int ni = 0; ni < 8; ni++)
#pragma unroll
            for (int t = 0; t < 4; t++) c[mi][ni][t] = 0.f;

#pragma unroll
    for (int ks = 0; ks < 2; ks++) {
        int rd = ks * 16 + rsel * 8 + rlo;
#pragma unroll
        for (int ng = 0; ng < 4; ng++) {
            int chunk = ng * 2 + csel;
            uint32_t r[4];
            ldsm_x4t(r, Ks + rd * 128 + ((chunk ^ (rd & 7)) << 4));
            uint32_t b0[2] = {r[0], r[2]}, b1[2] = {r[1], r[3]};
            mma_bf16(c[0][ng * 2],     qa[0][ks], b0);
            mma_bf16(c[0][ng * 2 + 1], qa[0][ks], b1);
            mma_bf16(c[1][ng * 2],     qa[1][ks], b0);
            mma_bf16(c[1][ng * 2 + 1], qa[1][ks], b1);
        }
    }

    // ---- softmax numerators + row sums + pack P a-frags ----
    float rs[2][2] = {{0.f, 0.f}, {0.f, 0.f}};
    uint32_t pa[2][4][4];
#pragma unroll
    for (int mi = 0; mi < 2; mi++)
#pragma unroll
        for (int ni = 0; ni < 8; ni++) {
            float e0 = __expf(c[mi][ni][0]);
            float e1 = __expf(c[mi][ni][1]);
            float e2 = __expf(c[mi][ni][2]);
            float e3 = __expf(c[mi][ni][3]);
            rs[mi][0] += e0 + e1;
            rs[mi][1] += e2 + e3;
            int ks = ni >> 1, half = ni & 1;
            pa[mi][ks][half * 2]     = pack_bf2(e0, e1);
            pa[mi][ks][half * 2 + 1] = pack_bf2(e2, e3);
        }
#pragma unroll
    for (int mi = 0; mi < 2; mi++)
#pragma unroll
        for (int j = 0; j < 2; j++) {
            rs[mi][j] += __shfl_xor_sync(0xffffffff, rs[mi][j], 1);
            rs[mi][j] += __shfl_xor_sync(0xffffffff, rs[mi][j], 2);
        }

    // ---- O = P V ----
    float o[2][4][4];
#pragma unroll
    for (int mi = 0; mi < 2; mi++)
#pragma unroll
        for (int nj = 0; nj < 4; nj++)
#pragma unroll
            for (int t = 0; t < 4; t++) o[mi][nj][t] = 0.f;

#pragma unroll
    for (int ks = 0; ks < 4; ks++) {
#pragma unroll
        for (int njg = 0; njg < 2; njg++) {
            int rd = njg * 16 + rsel * 8 + rlo;
            int chunk = ks * 2 + csel;
            uint32_t r[4];
            ldsm_x4(r, Vs + rd * 128 + ((chunk ^ (rd & 7)) << 4));
            uint32_t b0[2] = {r[0], r[1]}, b1[2] = {r[2], r[3]};
            mma_bf16(o[0][njg * 2],     pa[0][ks], b0);
            mma_bf16(o[0][njg * 2 + 1], pa[0][ks], b1);
            mma_bf16(o[1][njg * 2],     pa[1][ks], b0);
            mma_bf16(o[1][njg * 2 + 1], pa[1][ks], b1);
        }
    }

    // ---- normalize + write bf16 ----
    const int head = hp * 2 + whl;
    const size_t abase = ((size_t)b * 256 + head * 32) * HWC;
#pragma unroll
    for (int mi = 0; mi < 2; mi++) {
        const float inv0 = 1.f / rs[mi][0];
        const float inv1 = 1.f / rs[mi][1];
        const int t0 = mbase + mi * 16 + (lane >> 2);
        const size_t pos0 = (size_t)(h0 + (t0 >> 3)) * 256 + w0 + (t0 & 7);
        const size_t pos1 = pos0 + 256;     // token t0+8 = next spatial row
#pragma unroll
        for (int nj = 0; nj < 4; nj++) {
            const int d0 = nj * 8 + (lane & 3) * 2;
            __nv_bfloat16* p = attn + abase + (size_t)d0 * HWC;
            p[pos0]       = __float2bfloat16(o[mi][nj][0] * inv0);
            p[pos0 + HWC] = __float2bfloat16(o[mi][nj][1] * inv0);
            p[pos1]       = __float2bfloat16(o[mi][nj][2] * inv1);
            p[pos1 + HWC] = __float2bfloat16(o[mi][nj][3] * inv1);
        }
    }
}

// ---------------------------------------------------------------------------
// Launch
// ---------------------------------------------------------------------------
extern "C" void kernel_launch(void* const* d_in, const int* in_sizes, int n_in,
                              void* d_out, int out_size)
{
    const float* q    = (const float*)d_in[0];
    const float* gn_w = (const float*)d_in[1];
    const float* gn_b = (const float*)d_in[2];
    const float* q_w  = (const float*)d_in[3];
    const float* q_b  = (const float*)d_in[4];
    const float* k_w  = (const float*)d_in[5];
    const float* k_b  = (const float*)d_in[6];
    const float* v_w  = (const float*)d_in[7];
    const float* v_b  = (const float*)d_in[8];
    const float* o_w  = (const float*)d_in[9];
    const float* o_b  = (const float*)d_in[10];
    float* out = (float*)d_out;

    __nv_bfloat16 *p_wadjb, *p_owb, *p_qkv, *p_attn;
    float *p_badj;
    cudaGetSymbolAddress((void**)&p_wadjb, g_wadjb);
    cudaGetSymbolAddress((void**)&p_owb,   g_owb);
    cudaGetSymbolAddress((void**)&p_badj,  g_badj);
    cudaGetSymbolAddress((void**)&p_qkv,   g_qkv);
    cudaGetSymbolAddress((void**)&p_attn,  g_attn);

    cudaFuncSetAttribute((const void*)gemm_mma_kernel<6, false, float, __nv_bfloat16>,
                         cudaFuncAttributeMaxDynamicSharedMemorySize, SM_TOT);
    cudaFuncSetAttribute((const void*)gemm_mma_kernel<2, true, __nv_bfloat16, float>,
                         cudaFuncAttributeMaxDynamicSharedMemorySize, SM_TOT);

    // 1. GroupNorm stats
    gn_stats_kernel<<<NBAT * NGRP, 512>>>(q);

    // 2. Fold GN into QKV weights (bf16); o_w -> bf16
    prep_weights_kernel<<<dim3(768, NBAT), 256>>>(q_w, q_b, k_w, k_b, v_w, v_b, gn_w, gn_b);
    prep_ow_kernel<<<256, 256>>>(o_w);

    // 3. Fused (GN + QKV projection): [768 x 256] @ [256 x 65536] -> bf16
    gemm_mma_kernel<6, false, float, __nv_bfloat16><<<dim3(512, NBAT), 256, SM_TOT>>>(
        p_wadjb, 768LL * 256,
        p_badj, 768,
        q, (long long)CCH * HWC,
        p_qkv, 768LL * HWC,
        nullptr, 1.0f);

    // 4. Windowed attention (tensor-core)
    attn_mma_kernel<<<dim3(1024, 4, NBAT), 128>>>(p_qkv, p_attn);

    // 5. Output projection + residual + 2^-0.5 scale
    gemm_mma_kernel<2, true, __nv_bfloat16, float><<<dim3(512, NBAT), 256, SM_TOT>>>(
        p_owb, 0,
        o_b, 0,
        p_attn, (long long)CCH * HWC,
        out, (long long)CCH * HWC,
        q, 0.70710678118654752f);
}

// round 10
// speedup vs baseline: 8.3193x; 1.1327x over previous
#include <cuda_runtime.h>
#include <cuda_bf16.h>
#include <cstdint>
#include <cstddef>

// Problem constants
#define HWC   65536          // H*W = 256*256
#define CCH   256            // channels
#define NBAT  4
#define NHEAD 8
#define HD    32
#define NGRP  32
#define CPG   8              // channels per group

// ===========================================================================
// Helpers
// ===========================================================================
__device__ __forceinline__ uint32_t smem_u32(const void* p) {
    uint32_t a;
    asm("{ .reg .u64 t; cvta.to.shared.u64 t, %1; cvt.u32.u64 %0, t; }"
        : "=r"(a) : "l"(p));
    return a;
}
__device__ __forceinline__ void ldsm_x4(uint32_t* r, uint32_t addr) {
    asm volatile("ldmatrix.sync.aligned.m8n8.x4.shared.b16 {%0,%1,%2,%3}, [%4];"
        : "=r"(r[0]), "=r"(r[1]), "=r"(r[2]), "=r"(r[3]) : "r"(addr));
}
__device__ __forceinline__ void ldsm_x4t(uint32_t* r, uint32_t addr) {
    asm volatile("ldmatrix.sync.aligned.m8n8.x4.trans.shared.b16 {%0,%1,%2,%3}, [%4];"
        : "=r"(r[0]), "=r"(r[1]), "=r"(r[2]), "=r"(r[3]) : "r"(addr));
}
__device__ __forceinline__ void mma_bf16(float* c, const uint32_t* a, const uint32_t* b) {
    asm volatile("mma.sync.aligned.m16n8k16.row.col.f32.bf16.bf16.f32 "
        "{%0,%1,%2,%3}, {%4,%5,%6,%7}, {%8,%9}, {%0,%1,%2,%3};"
        : "+f"(c[0]), "+f"(c[1]), "+f"(c[2]), "+f"(c[3])
        : "r"(a[0]), "r"(a[1]), "r"(a[2]), "r"(a[3]), "r"(b[0]), "r"(b[1]));
}
__device__ __forceinline__ void cp16(uint32_t dst, const void* src) {
    asm volatile("cp.async.cg.shared.global [%0], [%1], 16;" :: "r"(dst), "l"(src));
}
#define CP_COMMIT() asm volatile("cp.async.commit_group;" ::: "memory")
#define CP_WAIT0()  asm volatile("cp.async.wait_group 0;" ::: "memory")

__device__ __forceinline__ void store2(float* p, float x, float y) {
    *(float2*)p = make_float2(x, y);
}
__device__ __forceinline__ void store2(__nv_bfloat16* p, float x, float y) {
    *(__nv_bfloat162*)p = __floats2bfloat162_rn(x, y);
}
__device__ __forceinline__ uint32_t pack_bf2(float x, float y) {
    __nv_bfloat162 h = __floats2bfloat162_rn(x, y);
    return *reinterpret_cast<uint32_t*>(&h);
}

// ---------------------------------------------------------------------------
// Scratch
// ---------------------------------------------------------------------------
__device__ float g_stats[NBAT * NGRP * 2];
__device__ __align__(16) __nv_bfloat16 g_wadjb[NBAT * 768 * 256];  // GN-folded QKV weights [b][m][k]
__device__ __align__(16) __nv_bfloat16 g_owb[256 * 256];           // o_w bf16 [o][c]
__device__ float g_badj[NBAT * 768];
__device__ __align__(16) __nv_bfloat16 g_qkv[(size_t)NBAT * 768 * HWC];  // [b][768][HW] bf16
__device__ __align__(16) __nv_bfloat16 g_attn[(size_t)NBAT * 256 * HWC]; // [b][C][HW] bf16

// ---------------------------------------------------------------------------
// K1: GroupNorm statistics
// ---------------------------------------------------------------------------
__global__ __launch_bounds__(512) void gn_stats_kernel(const float* __restrict__ q)
{
    int bg = blockIdx.x;
    const float4* base = (const float4*)(q + (size_t)bg * CPG * HWC);
    float s = 0.f, s2 = 0.f;
    for (int i = threadIdx.x; i < (CPG * HWC) / 4; i += 512) {
        float4 v = base[i];
        s  += v.x + v.y + v.z + v.w;
        s2 += v.x*v.x + v.y*v.y + v.z*v.z + v.w*v.w;
    }
    __shared__ float rs[512], rs2[512];
    rs[threadIdx.x] = s; rs2[threadIdx.x] = s2;
    __syncthreads();
    for (int off = 256; off > 0; off >>= 1) {
        if (threadIdx.x < off) {
            rs [threadIdx.x] += rs [threadIdx.x + off];
            rs2[threadIdx.x] += rs2[threadIdx.x + off];
        }
        __syncthreads();
    }
    if (threadIdx.x == 0) {
        const float invN = 1.f / (float)(CPG * HWC);
        float mean = rs[0] * invN;
        float var  = rs2[0] * invN - mean * mean;
        g_stats[bg * 2 + 0] = mean;
        g_stats[bg * 2 + 1] = rsqrtf(var + 1e-6f);
    }
}

// ---------------------------------------------------------------------------
// K2: fold GroupNorm into QKV weights -> bf16 [b][m][k]; 32^-0.5 folded into k.
// ---------------------------------------------------------------------------
__global__ __launch_bounds__(256) void prep_weights_kernel(
    const float* __restrict__ q_w, const float* __restrict__ q_b,
    const float* __restrict__ k_w, const float* __restrict__ k_b,
    const float* __restrict__ v_w, const float* __restrict__ v_b,
    const float* __restrict__ gn_w, const float* __restrict__ gn_b)
{
    int m = blockIdx.x;
    int b = blockIdx.y;
    int t = m >> 8, o = m & 255;
    const float* W; const float* Bv;
    if      (t == 0) { W = q_w; Bv = q_b; }
    else if (t == 1) { W = k_w; Bv = k_b; }
    else             { W = v_w; Bv = v_b; }
    const float KS = (t == 1) ? 0.17677669529663687f : 1.0f;

    int c = threadIdx.x;
    int g = c >> 3;
    float mean = g_stats[(b * NGRP + g) * 2 + 0];
    float rstd = g_stats[(b * NGRP + g) * 2 + 1];
    float sc = rstd * gn_w[c];
    float sh = gn_b[c] - mean * sc;
    float wv = W[o * 256 + c];

    g_wadjb[((size_t)b * 768 + m) * 256 + c] = __float2bfloat16(wv * sc * KS);

    __shared__ float red[256];
    red[c] = wv * sh;
    __syncthreads();
    for (int off = 128; off > 0; off >>= 1) {
        if (c < off) red[c] += red[c + off];
        __syncthreads();
    }
    if (c == 0) g_badj[(size_t)b * 768 + m] = (Bv[o] + red[0]) * KS;
}

__global__ __launch_bounds__(256) void prep_ow_kernel(const float* __restrict__ ow)
{
    int o = blockIdx.x, c = threadIdx.x;
    g_owb[o * 256 + c] = __float2bfloat16(ow[o * 256 + c]);
}

// ---------------------------------------------------------------------------
// K3/K5: bf16 mma.sync GEMM, 2 CTAs/SM.
// out[b][m][n] = sum_k A[m][k]*X[b][k][n] + bias.
//   Xs: [k=256][n=64] bf16, 128B rows, 16B-chunk XOR swizzle (ch ^ (k&7)). 32KB.
//   As: [m=128][k=128 half] bf16, 256B rows, ch ^ (m&7). 2 buffers x 32KB.
// 8 warps, warp tile 32m x 32n. Total smem 96KB -> 2 CTAs/SM (16 warps).
// ---------------------------------------------------------------------------
#define SM_X    0
#define SM_A    32768
#define SM_TOT  98304

// stage X tile: fp32 source (convert to bf16, manual stores)
__device__ __forceinline__ void stage_x(char* smem, const float* Xb, int tid)
{
#pragma unroll 4
    for (int it = 0; it < 16; it++) {
        int idx = tid + it * 256;           // 4096 float4s = 256k x 16 groups
        int k = idx >> 4, n4 = idx & 15;
        float4 v = *(const float4*)(Xb + (size_t)k * HWC + n4 * 4);
        uint2 u;
        u.x = pack_bf2(v.x, v.y);
        u.y = pack_bf2(v.z, v.w);
        int chunk = n4 >> 1, half = n4 & 1;
        *(uint2*)(smem + SM_X + k * 128 + (((chunk ^ (k & 7)) << 4) + half * 8)) = u;
    }
}
// stage X tile: bf16 source (cp.async straight copies)
__device__ __forceinline__ void stage_x(char* smem, const __nv_bfloat16* Xb, int tid)
{
    const uint32_t sb = smem_u32(smem);
#pragma unroll 4
    for (int i = tid; i < 2048; i += 256) {
        int k = i >> 3, g = i & 7;
        cp16(sb + SM_X + k * 128 + ((g ^ (k & 7)) << 4),
             Xb + (size_t)k * HWC + g * 8);
    }
}
// stage A half-tile: 128m x 128k bf16 (Asrc points at [m0][k_half0])
__device__ __forceinline__ void stage_a(uint32_t sb, const __nv_bfloat16* Asrc,
                                        uint32_t buf, int tid)
{
#pragma unroll 4
    for (int i = tid; i < 2048; i += 256) {
        int m = i >> 4, ch = i & 15;
        cp16(sb + SM_A + buf * 32768 + m * 256 + ((ch ^ (m & 7)) << 4),
             Asrc + (size_t)m * 256 + ch * 8);
    }
}

template <int MT, bool RES, typename TIN, typename TOUT>
__global__ __launch_bounds__(256, 2) void gemm_mma_kernel(
    const __nv_bfloat16* __restrict__ Abf, long long Abs,
    const float* __restrict__ bias, int biasBs,
    const TIN* __restrict__ X, long long Xbs,
    TOUT* __restrict__ out, long long Obs,
    const float* __restrict__ res, float scale)
{
    extern __shared__ char smem[];
    const uint32_t sb = smem_u32(smem);
    const int tid = threadIdx.x, wid = tid >> 5, lane = tid & 31;
    const int b = blockIdx.y;
    const int n0 = blockIdx.x * 64;

    const __nv_bfloat16* Ab = Abf + (size_t)b * Abs;

    // ---- prologue: stage X + issue A (mt=0, half=0) ----
    stage_x(smem, X + (size_t)b * Xbs + n0, tid);
    stage_a(sb, Ab, 0, tid);
    CP_COMMIT();

    // ---- per-lane ldmatrix invariants ----
    const int wm = (wid & 3) * 32;               // warp m offset
    const int wn = (wid >> 2) * 32;              // warp n offset
    const int arow = wm + (lane & 15);
    const int asel = lane >> 4;
    const int ar7  = arow & 7;
    const int gg = lane >> 3, ll = lane & 7;
    const int kbl = (gg & 1) * 8 + ll;           // k row offset within 16-step
    uint32_t bCn[2];
#pragma unroll
    for (int j = 0; j < 2; j++) bCn[j] = (uint32_t)((wn >> 3) + j * 2 + (gg >> 1));
    const int er = lane >> 2, ec = (lane & 3) * 2;

    uint32_t stage = 0;
    for (int mt = 0; mt < MT; mt++) {
        float c[2][4][4];
#pragma unroll
        for (int mi = 0; mi < 2; mi++)
#pragma unroll
            for (int ni = 0; ni < 4; ni++)
#pragma unroll
                for (int t = 0; t < 4; t++) c[mi][ni][t] = 0.f;

#pragma unroll
        for (int half = 0; half < 2; half++) {
            CP_WAIT0();
            __syncthreads();
            // issue next half into the other buffer
            int nmt = mt, nhalf = half + 1;
            if (nhalf == 2) { nmt = mt + 1; nhalf = 0; }
            if (nmt < MT) {
                stage_a(sb, Ab + (size_t)nmt * 32768 + nhalf * 128, stage ^ 1, tid);
                CP_COMMIT();
            }
            const uint32_t abuf = sb + SM_A + stage * 32768;

#pragma unroll
            for (int ks = 0; ks < 8; ks++) {
                uint32_t a0[4], a1[4];
                const uint32_t aoff = (uint32_t)(((ks * 2 + asel) ^ ar7) << 4);
                ldsm_x4(a0, abuf + (uint32_t)arow * 256 + aoff);
                ldsm_x4(a1, abuf + (uint32_t)(arow + 16) * 256 + aoff);
                const int kb = half * 128 + ks * 16 + kbl;       // global k row
                uint32_t bf[4][2];
#pragma unroll
                for (int j = 0; j < 2; j++) {
                    uint32_t r[4];
                    ldsm_x4t(r, sb + SM_X + (uint32_t)kb * 128
                                + ((bCn[j] ^ (uint32_t)(kb & 7)) << 4));
                    bf[2 * j][0] = r[0];     bf[2 * j][1] = r[1];
                    bf[2 * j + 1][0] = r[2]; bf[2 * j + 1][1] = r[3];
                }
#pragma unroll
                for (int ni = 0; ni < 4; ni++) {
                    mma_bf16(c[0][ni], a0, bf[ni]);
                    mma_bf16(c[1][ni], a1, bf[ni]);
                }
            }
            stage ^= 1;
        }

        // ---- epilogue ----
#pragma unroll
        for (int mi = 0; mi < 2; mi++) {
            const int m0g = mt * 128 + wm + mi * 16 + er;
            const float bv0 = bias[(size_t)b * biasBs + m0g];
            const float bv1 = bias[(size_t)b * biasBs + m0g + 8];
            TOUT* o0 = out + (size_t)b * Obs + (size_t)m0g * HWC + n0 + wn + ec;
            TOUT* o1 = o0 + 8 * HWC;
            const float* r0 = RES ? (res + (size_t)b * Obs + (size_t)m0g * HWC + n0 + wn + ec)
                                  : nullptr;
            const float* r1 = RES ? (r0 + 8 * HWC) : nullptr;
#pragma unroll
            for (int ni = 0; ni < 4; ni++) {
                float x0 = c[mi][ni][0] + bv0, y0 = c[mi][ni][1] + bv0;
                float x1 = c[mi][ni][2] + bv1, y1 = c[mi][ni][3] + bv1;
                if (RES) {
                    float2 q0 = *(const float2*)(r0 + ni * 8);
                    float2 q1 = *(const float2*)(r1 + ni * 8);
                    x0 = (x0 + q0.x) * scale; y0 = (y0 + q0.y) * scale;
                    x1 = (x1 + q1.x) * scale; y1 = (y1 + q1.y) * scale;
                }
                store2(o0 + ni * 8, x0, y0);
                store2(o1 + ni * 8, x1, y1);
            }
        }
    }
}

// ---------------------------------------------------------------------------
// K4: windowed MHA with mma.sync bf16 (unchanged from R8 — validated).
// ---------------------------------------------------------------------------
__global__ __launch_bounds__(128) void attn_mma_kernel(
    const __nv_bfloat16* __restrict__ qkv, __nv_bfloat16* __restrict__ attn)
{
    __shared__ __align__(16) char smem[24576];
    const int tid = threadIdx.x, wid = tid >> 5, lane = tid & 31;
    const int win = blockIdx.x, hp = blockIdx.y, b = blockIdx.z;
    const int wy = win >> 5, wx = win & 31;
    const int h0 = wy * 8, w0 = wx * 8;

    {
        const size_t gbase = (size_t)b * 768 * HWC;
#pragma unroll
        for (int idx = tid; idx < 1536; idx += 128) {
            int tr = idx & 7, d = (idx >> 3) & 31, whl = (idx >> 8) & 1, t = idx >> 9;
            int ch = t * 256 + (hp * 2 + whl) * 32 + d;
            uint4 v = *(const uint4*)(qkv + gbase + (size_t)ch * HWC
                                      + (size_t)(h0 + tr) * 256 + w0);
            *(uint4*)(smem + whl * 12288 + t * 4096 + d * 128 + ((tr ^ (d & 7)) << 4)) = v;
        }
    }
    __syncthreads();

    const uint32_t sb = smem_u32(smem);
    const int whl = wid >> 1, wpair = wid & 1;
    const uint32_t Qs = sb + whl * 12288;
    const uint32_t Ks = Qs + 4096;
    const uint32_t Vs = Qs + 8192;
    const int mbase = wpair * 32;

    const int rlo = lane & 7, rsel = lane >> 4, csel = (lane >> 3) & 1;

    uint32_t qa[2][2][4];
#pragma unroll
    for (int mi = 0; mi < 2; mi++)
#pragma unroll
        for (int ks = 0; ks < 2; ks++) {
            int rd = ks * 16 + rsel * 8 + rlo;
            int chunk = (mbase >> 3) + mi * 2 + csel;
            ldsm_x4t(qa[mi][ks], Qs + rd * 128 + ((chunk ^ (rd & 7)) << 4));
        }

    float c[2][8][4];
#pragma unroll
    for (int mi = 0; mi < 2; mi++)
#pragma unroll
        for (int ni = 0; ni < 8; ni++)
#pragma unroll
            for (int t = 0; t < 4; t++) c[mi][ni][t] = 0.f;

#pragma unroll
    for (int ks = 0; ks < 2; ks++) {
        int rd = ks * 16 + rsel * 8 + rlo;
#pragma unroll
        for (int ng = 0; ng < 4; ng++) {
            int chunk = ng * 2 + csel;
            uint32_t r[4];
            ldsm_x4t(r, Ks + rd * 128 + ((chunk ^ (rd & 7)) << 4));
            uint32_t b0[2] = {r[0], r[2]}, b1[2] = {r[1], r[3]};
            mma_bf16(c[0][ng * 2],     qa[0][ks], b0);
            mma_bf16(c[0][ng * 2 + 1], qa[0][ks], b1);
            mma_bf16(c[1][ng * 2],     qa[1][ks], b0);
            mma_bf16(c[1][ng * 2 + 1], qa[1][ks], b1);
        }
    }

    float rs[2][2] = {{0.f, 0.f}, {0.f, 0.f}};
    uint32_t pa[2][4][4];
#pragma unroll
    for (int mi = 0; mi < 2; mi++)
#pragma unroll
        for (int ni = 0; ni < 8; ni++) {
            float e0 = __expf(c[mi][ni][0]);
            float e1 = __expf(c[mi][ni][1]);
            float e2 = __expf(c[mi][ni][2]);
            float e3 = __expf(c[mi][ni][3]);
            rs[mi][0] += e0 + e1;
            rs[mi][1] += e2 + e3;
            int ks = ni >> 1, half = ni & 1;
            pa[mi][ks][half * 2]     = pack_bf2(e0, e1);
            pa[mi][ks][half * 2 + 1] = pack_bf2(e2, e3);
        }
#pragma unroll
    for (int mi = 0; mi < 2; mi++)
#pragma unroll
        for (int j = 0; j < 2; j++) {
            rs[mi][j] += __shfl_xor_sync(0xffffffff, rs[mi][j], 1);
            rs[mi][j] += __shfl_xor_sync(0xffffffff, rs[mi][j], 2);
        }

    float o[2][4][4];
#pragma unroll
    for (int mi = 0; mi < 2; mi++)
#pragma unroll
        for (int nj = 0; nj < 4; nj++)
#pragma unroll
            for (int t = 0; t < 4; t++) o[mi][nj][t] = 0.f;

#pragma unroll
    for (int ks = 0; ks < 4; ks++) {
#pragma unroll
        for (int njg = 0; njg < 2; njg++) {
            int rd = njg * 16 + rsel * 8 + rlo;
            int chunk = ks * 2 + csel;
            uint32_t r[4];
            ldsm_x4(r, Vs + rd * 128 + ((chunk ^ (rd & 7)) << 4));
            uint32_t b0[2] = {r[0], r[1]}, b1[2] = {r[2], r[3]};
            mma_bf16(o[0][njg * 2],     pa[0][ks], b0);
            mma_bf16(o[0][njg * 2 + 1], pa[0][ks], b1);
            mma_bf16(o[1][njg * 2],     pa[1][ks], b0);
            mma_bf16(o[1][njg * 2 + 1], pa[1][ks], b1);
        }
    }

    const int head = hp * 2 + whl;
    const size_t abase = ((size_t)b * 256 + head * 32) * HWC;
#pragma unroll
    for (int mi = 0; mi < 2; mi++) {
        const float inv0 = 1.f / rs[mi][0];
        const float inv1 = 1.f / rs[mi][1];
        const int t0 = mbase + mi * 16 + (lane >> 2);
        const size_t pos0 = (size_t)(h0 + (t0 >> 3)) * 256 + w0 + (t0 & 7);
        const size_t pos1 = pos0 + 256;
#pragma unroll
        for (int nj = 0; nj < 4; nj++) {
            const int d0 = nj * 8 + (lane & 3) * 2;
            __nv_bfloat16* p = attn + abase + (size_t)d0 * HWC;
            p[pos0]       = __float2bfloat16(o[mi][nj][0] * inv0);
            p[pos0 + HWC] = __float2bfloat16(o[mi][nj][1] * inv0);
            p[pos1]       = __float2bfloat16(o[mi][nj][2] * inv1);
            p[pos1 + HWC] = __float2bfloat16(o[mi][nj][3] * inv1);
        }
    }
}

// ---------------------------------------------------------------------------
// Launch
// ---------------------------------------------------------------------------
extern "C" void kernel_launch(void* const* d_in, const int* in_sizes, int n_in,
                              void* d_out, int out_size)
{
    const float* q    = (const float*)d_in[0];
    const float* gn_w = (const float*)d_in[1];
    const float* gn_b = (const float*)d_in[2];
    const float* q_w  = (const float*)d_in[3];
    const float* q_b  = (const float*)d_in[4];
    const float* k_w  = (const float*)d_in[5];
    const float* k_b  = (const float*)d_in[6];
    const float* v_w  = (const float*)d_in[7];
    const float* v_b  = (const float*)d_in[8];
    const float* o_w  = (const float*)d_in[9];
    const float* o_b  = (const float*)d_in[10];
    float* out = (float*)d_out;

    __nv_bfloat16 *p_wadjb, *p_owb, *p_qkv, *p_attn;
    float *p_badj;
    cudaGetSymbolAddress((void**)&p_wadjb, g_wadjb);
    cudaGetSymbolAddress((void**)&p_owb,   g_owb);
    cudaGetSymbolAddress((void**)&p_badj,  g_badj);
    cudaGetSymbolAddress((void**)&p_qkv,   g_qkv);
    cudaGetSymbolAddress((void**)&p_attn,  g_attn);

    cudaFuncSetAttribute((const void*)gemm_mma_kernel<6, false, float, __nv_bfloat16>,
                         cudaFuncAttributeMaxDynamicSharedMemorySize, SM_TOT);
    cudaFuncSetAttribute((const void*)gemm_mma_kernel<2, true, __nv_bfloat16, float>,
                         cudaFuncAttributeMaxDynamicSharedMemorySize, SM_TOT);

    // 1. GroupNorm stats
    gn_stats_kernel<<<NBAT * NGRP, 512>>>(q);

    // 2. Fold GN into QKV weights (bf16); o_w -> bf16
    prep_weights_kernel<<<dim3(768, NBAT), 256>>>(q_w, q_b, k_w, k_b, v_w, v_b, gn_w, gn_b);
    prep_ow_kernel<<<256, 256>>>(o_w);

    // 3. Fused (GN + QKV projection): [768 x 256] @ [256 x 65536] -> bf16
    gemm_mma_kernel<6, false, float, __nv_bfloat16><<<dim3(1024, NBAT), 256, SM_TOT>>>(
        p_wadjb, 768LL * 256,
        p_badj, 768,
        q, (long long)CCH * HWC,
        p_qkv, 768LL * HWC,
        nullptr, 1.0f);

    // 4. Windowed attention (tensor-core)
    attn_mma_kernel<<<dim3(1024, 4, NBAT), 128>>>(p_qkv, p_attn);

    // 5. Output projection + residual + 2^-0.5 scale
    gemm_mma_kernel<2, true, __nv_bfloat16, float><<<dim3(1024, NBAT), 256, SM_TOT>>>(
        p_owb, 0,
        o_b, 0,
        p_attn, (long long)CCH * HWC,
        out, (long long)CCH * HWC,
        q, 0.70710678118654752f);
}

// round 12
// speedup vs baseline: 8.6176x; 1.0359x over previous
#include <cuda_runtime.h>
#include <cuda_bf16.h>
#include <cstdint>
#include <cstddef>

// Problem constants
#define HWC   65536          // H*W = 256*256
#define CCH   256            // channels
#define NBAT  4
#define NHEAD 8
#define HD    32
#define NGRP  32
#define CPG   8              // channels per group

// ===========================================================================
// Helpers
// ===========================================================================
__device__ __forceinline__ uint32_t smem_u32(const void* p) {
    uint32_t a;
    asm("{ .reg .u64 t; cvta.to.shared.u64 t, %1; cvt.u32.u64 %0, t; }"
        : "=r"(a) : "l"(p));
    return a;
}
__device__ __forceinline__ void ldsm_x4(uint32_t* r, uint32_t addr) {
    asm volatile("ldmatrix.sync.aligned.m8n8.x4.shared.b16 {%0,%1,%2,%3}, [%4];"
        : "=r"(r[0]), "=r"(r[1]), "=r"(r[2]), "=r"(r[3]) : "r"(addr));
}
__device__ __forceinline__ void ldsm_x4t(uint32_t* r, uint32_t addr) {
    asm volatile("ldmatrix.sync.aligned.m8n8.x4.trans.shared.b16 {%0,%1,%2,%3}, [%4];"
        : "=r"(r[0]), "=r"(r[1]), "=r"(r[2]), "=r"(r[3]) : "r"(addr));
}
__device__ __forceinline__ void mma_bf16(float* c, const uint32_t* a, const uint32_t* b) {
    asm volatile("mma.sync.aligned.m16n8k16.row.col.f32.bf16.bf16.f32 "
        "{%0,%1,%2,%3}, {%4,%5,%6,%7}, {%8,%9}, {%0,%1,%2,%3};"
        : "+f"(c[0]), "+f"(c[1]), "+f"(c[2]), "+f"(c[3])
        : "r"(a[0]), "r"(a[1]), "r"(a[2]), "r"(a[3]), "r"(b[0]), "r"(b[1]));
}
__device__ __forceinline__ void cp16(uint32_t dst, const void* src) {
    asm volatile("cp.async.cg.shared.global [%0], [%1], 16;" :: "r"(dst), "l"(src));
}
#define CP_COMMIT() asm volatile("cp.async.commit_group;" ::: "memory")
#define CP_WAIT0()  asm volatile("cp.async.wait_group 0;" ::: "memory")

__device__ __forceinline__ void store2(float* p, float x, float y) {
    *(float2*)p = make_float2(x, y);
}
__device__ __forceinline__ void store2(__nv_bfloat16* p, float x, float y) {
    *(__nv_bfloat162*)p = __floats2bfloat162_rn(x, y);
}
__device__ __forceinline__ uint32_t pack_bf2(float x, float y) {
    __nv_bfloat162 h = __floats2bfloat162_rn(x, y);
    return *reinterpret_cast<uint32_t*>(&h);
}

// ---------------------------------------------------------------------------
// Scratch
// ---------------------------------------------------------------------------
__device__ float g_stats[NBAT * NGRP * 2];
__device__ __align__(16) __nv_bfloat16 g_wadjb[NBAT * 768 * 256];  // GN-folded QKV weights [b][m][k]
__device__ __align__(16) __nv_bfloat16 g_owb[256 * 256];           // o_w bf16 [o][c]
__device__ float g_badj[NBAT * 768];
__device__ __align__(16) __nv_bfloat16 g_qkv[(size_t)NBAT * 768 * HWC];  // [b][768][HW] bf16
__device__ __align__(16) __nv_bfloat16 g_attn[(size_t)NBAT * 256 * HWC]; // [b][C][HW] bf16

// ---------------------------------------------------------------------------
// K1: GroupNorm statistics
// ---------------------------------------------------------------------------
__global__ __launch_bounds__(512) void gn_stats_kernel(const float* __restrict__ q)
{
    int bg = blockIdx.x;
    const float4* base = (const float4*)(q + (size_t)bg * CPG * HWC);
    float s = 0.f, s2 = 0.f;
    for (int i = threadIdx.x; i < (CPG * HWC) / 4; i += 512) {
        float4 v = base[i];
        s  += v.x + v.y + v.z + v.w;
        s2 += v.x*v.x + v.y*v.y + v.z*v.z + v.w*v.w;
    }
    __shared__ float rs[512], rs2[512];
    rs[threadIdx.x] = s; rs2[threadIdx.x] = s2;
    __syncthreads();
    for (int off = 256; off > 0; off >>= 1) {
        if (threadIdx.x < off) {
            rs [threadIdx.x] += rs [threadIdx.x + off];
            rs2[threadIdx.x] += rs2[threadIdx.x + off];
        }
        __syncthreads();
    }
    if (threadIdx.x == 0) {
        const float invN = 1.f / (float)(CPG * HWC);
        float mean = rs[0] * invN;
        float var  = rs2[0] * invN - mean * mean;
        g_stats[bg * 2 + 0] = mean;
        g_stats[bg * 2 + 1] = rsqrtf(var + 1e-6f);
    }
}

// ---------------------------------------------------------------------------
// K2: fold GroupNorm into QKV weights -> bf16 [b][m][k]; 32^-0.5 folded into k.
// ---------------------------------------------------------------------------
__global__ __launch_bounds__(256) void prep_weights_kernel(
    const float* __restrict__ q_w, const float* __restrict__ q_b,
    const float* __restrict__ k_w, const float* __restrict__ k_b,
    const float* __restrict__ v_w, const float* __restrict__ v_b,
    const float* __restrict__ gn_w, const float* __restrict__ gn_b)
{
    int m = blockIdx.x;
    int b = blockIdx.y;
    int t = m >> 8, o = m & 255;
    const float* W; const float* Bv;
    if      (t == 0) { W = q_w; Bv = q_b; }
    else if (t == 1) { W = k_w; Bv = k_b; }
    else             { W = v_w; Bv = v_b; }
    const float KS = (t == 1) ? 0.17677669529663687f : 1.0f;

    int c = threadIdx.x;
    int g = c >> 3;
    float mean = g_stats[(b * NGRP + g) * 2 + 0];
    float rstd = g_stats[(b * NGRP + g) * 2 + 1];
    float sc = rstd * gn_w[c];
    float sh = gn_b[c] - mean * sc;
    float wv = W[o * 256 + c];

    g_wadjb[((size_t)b * 768 + m) * 256 + c] = __float2bfloat16(wv * sc * KS);

    __shared__ float red[256];
    red[c] = wv * sh;
    __syncthreads();
    for (int off = 128; off > 0; off >>= 1) {
        if (c < off) red[c] += red[c + off];
        __syncthreads();
    }
    if (c == 0) g_badj[(size_t)b * 768 + m] = (Bv[o] + red[0]) * KS;
}

__global__ __launch_bounds__(256) void prep_ow_kernel(const float* __restrict__ ow)
{
    int o = blockIdx.x, c = threadIdx.x;
    g_owb[o * 256 + c] = __float2bfloat16(ow[o * 256 + c]);
}

// ---------------------------------------------------------------------------
// K3/K5: bf16 mma.sync GEMM, 2 CTAs/SM, CTA tile 128m x 128n.
// out[b][m][n] = sum_k A[m][k]*X[b][k][n] + bias.
//   Xs: [k=256][n=128] bf16, 256B rows, 16B-chunk XOR swizzle (ch ^ (k&7)). 64KB.
//   As: quarter-K tiles [m=128][k=64] bf16, 128B rows, ch ^ (m&7).
//       2 buffers x 16KB, cp.async prefetch pipeline.
// 8 warps (4m x 2n), warp tile 32m x 64n -> 6 LDSM : 16 HMMA per k-step.
// Total smem 96KB -> 2 CTAs/SM.
// ---------------------------------------------------------------------------
#define SM_X    0
#define SM_A    65536
#define SM_TOT  98304

// stage X tile: fp32 source (convert to bf16, manual stores)
__device__ __forceinline__ void stage_x(char* smem, const float* Xb, int tid)
{
#pragma unroll 4
    for (int it = 0; it < 32; it++) {
        int idx = tid + it * 256;             // 8192 float4 = 256k x 32 groups
        int k = idx >> 5, n4 = idx & 31;
        float4 v = *(const float4*)(Xb + (size_t)k * HWC + n4 * 4);
        uint2 u;
        u.x = pack_bf2(v.x, v.y);
        u.y = pack_bf2(v.z, v.w);
        int chunk = n4 >> 1, half = n4 & 1;
        *(uint2*)(smem + SM_X + k * 256 + (((chunk ^ (k & 7)) << 4) + half * 8)) = u;
    }
}
// stage X tile: bf16 source (cp.async straight copies)
__device__ __forceinline__ void stage_x(char* smem, const __nv_bfloat16* Xb, int tid)
{
    const uint32_t sb = smem_u32(smem);
#pragma unroll 4
    for (int i = tid; i < 4096; i += 256) {
        int k = i >> 4, g = i & 15;
        cp16(sb + SM_X + k * 256 + ((g ^ (k & 7)) << 4),
             Xb + (size_t)k * HWC + g * 8);
    }
}
// stage A quarter tile: 128m x 64k bf16 (Asrc points at [m0][k_quarter0])
__device__ __forceinline__ void stage_aq(uint32_t sb, const __nv_bfloat16* Asrc,
                                         uint32_t buf, int tid)
{
#pragma unroll
    for (int i = tid; i < 1024; i += 256) {
        int m = i >> 3, ch = i & 7;
        cp16(sb + SM_A + buf * 16384 + m * 128 + ((ch ^ (m & 7)) << 4),
             Asrc + (size_t)m * 256 + ch * 8);
    }
}

template <int MT, bool RES, typename TIN, typename TOUT>
__global__ __launch_bounds__(256, 2) void gemm_mma_kernel(
    const __nv_bfloat16* __restrict__ Abf, long long Abs,
    const float* __restrict__ bias, int biasBs,
    const TIN* __restrict__ X, long long Xbs,
    TOUT* __restrict__ out, long long Obs,
    const float* __restrict__ res, float scale)
{
    extern __shared__ char smem[];
    const uint32_t sb = smem_u32(smem);
    const int tid = threadIdx.x, wid = tid >> 5, lane = tid & 31;
    const int b = blockIdx.y;
    const int n0 = blockIdx.x * 128;

    const __nv_bfloat16* Ab = Abf + (size_t)b * Abs;

    // ---- prologue: stage X + issue A quarter 0 ----
    stage_x(smem, X + (size_t)b * Xbs + n0, tid);
    stage_aq(sb, Ab, 0, tid);
    CP_COMMIT();

    // ---- per-lane ldmatrix invariants ----
    const int wm = (wid & 3) * 32;               // warp m offset
    const int wn = (wid >> 2) * 64;              // warp n offset
    const int arow = wm + (lane & 15);
    const int asel = lane >> 4;
    const int ar7  = arow & 7;
    const int gg = lane >> 3, ll = lane & 7;
    const int kbl = (gg & 1) * 8 + ll;           // k row offset within 16-step
    const int br7 = kbl & 7;
    uint32_t bBase[4];
#pragma unroll
    for (int j = 0; j < 4; j++) {
        int cn = (wn >> 3) + j * 2 + (gg >> 1);
        bBase[j] = sb + SM_X + (uint32_t)kbl * 256 + (uint32_t)((cn ^ br7) << 4);
    }
    const int er = lane >> 2, ec = (lane & 3) * 2;

    for (int mt = 0; mt < MT; mt++) {
        float c[2][8][4];
#pragma unroll
        for (int mi = 0; mi < 2; mi++)
#pragma unroll
            for (int ni = 0; ni < 8; ni++)
#pragma unroll
                for (int t = 0; t < 4; t++) c[mi][ni][t] = 0.f;

#pragma unroll
        for (int q = 0; q < 4; q++) {
            const int qi = mt * 4 + q;
            CP_WAIT0();
            __syncthreads();
            const int nqi = qi + 1;
            if (nqi < MT * 4) {
                stage_aq(sb, Ab + (size_t)(nqi >> 2) * 32768 + (nqi & 3) * 64,
                         (uint32_t)(nqi & 1), tid);
                CP_COMMIT();
            }
            const uint32_t abuf = sb + SM_A + (uint32_t)(qi & 1) * 16384;

#pragma unroll
            for (int ksl = 0; ksl < 4; ksl++) {
                uint32_t a0[4], a1[4];
                const uint32_t aoff = (uint32_t)(((ksl * 2 + asel) ^ ar7) << 4);
                ldsm_x4(a0, abuf + (uint32_t)arow * 128 + aoff);
                ldsm_x4(a1, abuf + (uint32_t)(arow + 16) * 128 + aoff);
                const uint32_t xoff = (uint32_t)(q * 16384 + ksl * 4096);
                uint32_t bf[8][2];
#pragma unroll
                for (int j = 0; j < 4; j++) {
                    uint32_t r[4];
                    ldsm_x4t(r, bBase[j] + xoff);
                    bf[2 * j][0] = r[0];     bf[2 * j][1] = r[1];
                    bf[2 * j + 1][0] = r[2]; bf[2 * j + 1][1] = r[3];
                }
#pragma unroll
                for (int ni = 0; ni < 8; ni++) {
                    mma_bf16(c[0][ni], a0, bf[ni]);
                    mma_bf16(c[1][ni], a1, bf[ni]);
                }
            }
        }

        // ---- epilogue ----
#pragma unroll
        for (int mi = 0; mi < 2; mi++) {
            const int m0g = mt * 128 + wm + mi * 16 + er;
            const float bv0 = bias[(size_t)b * biasBs + m0g];
            const float bv1 = bias[(size_t)b * biasBs + m0g + 8];
            TOUT* o0 = out + (size_t)b * Obs + (size_t)m0g * HWC + n0 + wn + ec;
            TOUT* o1 = o0 + 8 * HWC;
            const float* r0 = RES ? (res + (size_t)b * Obs + (size_t)m0g * HWC + n0 + wn + ec)
                                  : nullptr;
            const float* r1 = RES ? (r0 + 8 * HWC) : nullptr;
#pragma unroll
            for (int ni = 0; ni < 8; ni++) {
                float x0 = c[mi][ni][0] + bv0, y0 = c[mi][ni][1] + bv0;
                float x1 = c[mi][ni][2] + bv1, y1 = c[mi][ni][3] + bv1;
                if (RES) {
                    float2 q0 = *(const float2*)(r0 + ni * 8);
                    float2 q1 = *(const float2*)(r1 + ni * 8);
                    x0 = (x0 + q0.x) * scale; y0 = (y0 + q0.y) * scale;
                    x1 = (x1 + q1.x) * scale; y1 = (y1 + q1.y) * scale;
                }
                store2(o0 + ni * 8, x0, y0);
                store2(o1 + ni * 8, x1, y1);
            }
        }
    }
}

// ---------------------------------------------------------------------------
// K4: windowed MHA with mma.sync bf16 (unchanged — validated).
// ---------------------------------------------------------------------------
__global__ __launch_bounds__(128) void attn_mma_kernel(
    const __nv_bfloat16* __restrict__ qkv, __nv_bfloat16* __restrict__ attn)
{
    __shared__ __align__(16) char smem[24576];
    const int tid = threadIdx.x, wid = tid >> 5, lane = tid & 31;
    const int win = blockIdx.x, hp = blockIdx.y, b = blockIdx.z;
    const int wy = win >> 5, wx = win & 31;
    const int h0 = wy * 8, w0 = wx * 8;

    {
        const size_t gbase = (size_t)b * 768 * HWC;
#pragma unroll
        for (int idx = tid; idx < 1536; idx += 128) {
            int tr = idx & 7, d = (idx >> 3) & 31, whl = (idx >> 8) & 1, t = idx >> 9;
            int ch = t * 256 + (hp * 2 + whl) * 32 + d;
            uint4 v = *(const uint4*)(qkv + gbase + (size_t)ch * HWC
                                      + (size_t)(h0 + tr) * 256 + w0);
            *(uint4*)(smem + whl * 12288 + t * 4096 + d * 128 + ((tr ^ (d & 7)) << 4)) = v;
        }
    }
    __syncthreads();

    const uint32_t sb = smem_u32(smem);
    const int whl = wid >> 1, wpair = wid & 1;
    const uint32_t Qs = sb + whl * 12288;
    const uint32_t Ks = Qs + 4096;
    const uint32_t Vs = Qs + 8192;
    const int mbase = wpair * 32;

    const int rlo = lane & 7, rsel = lane >> 4, csel = (lane >> 3) & 1;

    uint32_t qa[2][2][4];
#pragma unroll
    for (int mi = 0; mi < 2; mi++)
#pragma unroll
        for (int ks = 0; ks < 2; ks++) {
            int rd = ks * 16 + rsel * 8 + rlo;
            int chunk = (mbase >> 3) + mi * 2 + csel;
            ldsm_x4t(qa[mi][ks], Qs + rd * 128 + ((chunk ^ (rd & 7)) << 4));
        }

    float c[2][8][4];
#pragma unroll
    for (int mi = 0; mi < 2; mi++)
#pragma unroll
        for (int ni = 0; ni < 8; ni++)
#pragma unroll
            for (int t = 0; t < 4; t++) c[mi][ni][t] = 0.f;

#pragma unroll
    for (int ks = 0; ks < 2; ks++) {
        int rd = ks * 16 + rsel * 8 + rlo;
#pragma unroll
        for (int ng = 0; ng < 4; ng++) {
            int chunk = ng * 2 + csel;
            uint32_t r[4];
            ldsm_x4t(r, Ks + rd * 128 + ((chunk ^ (rd & 7)) << 4));
            uint32_t b0[2] = {r[0], r[2]}, b1[2] = {r[1], r[3]};
            mma_bf16(c[0][ng * 2],     qa[0][ks], b0);
            mma_bf16(c[0][ng * 2 + 1], qa[0][ks], b1);
            mma_bf16(c[1][ng * 2],     qa[1][ks], b0);
            mma_bf16(c[1][ng * 2 + 1], qa[1][ks], b1);
        }
    }

    float rs[2][2] = {{0.f, 0.f}, {0.f, 0.f}};
    uint32_t pa[2][4][4];
#pragma unroll
    for (int mi = 0; mi < 2; mi++)
#pragma unroll
        for (int ni = 0; ni < 8; ni++) {
            float e0 = __expf(c[mi][ni][0]);
            float e1 = __expf(c[mi][ni][1]);
            float e2 = __expf(c[mi][ni][2]);
            float e3 = __expf(c[mi][ni][3]);
            rs[mi][0] += e0 + e1;
            rs[mi][1] += e2 + e3;
            int ks = ni >> 1, half = ni & 1;
            pa[mi][ks][half * 2]     = pack_bf2(e0, e1);
            pa[mi][ks][half * 2 + 1] = pack_bf2(e2, e3);
        }
#pragma unroll
    for (int mi = 0; mi < 2; mi++)
#pragma unroll
        for (int j = 0; j < 2; j++) {
            rs[mi][j] += __shfl_xor_sync(0xffffffff, rs[mi][j], 1);
            rs[mi][j] += __shfl_xor_sync(0xffffffff, rs[mi][j], 2);
        }

    float o[2][4][4];
#pragma unroll
    for (int mi = 0; mi < 2; mi++)
#pragma unroll
        for (int nj = 0; nj < 4; nj++)
#pragma unroll
            for (int t = 0; t < 4; t++) o[mi][nj][t] = 0.f;

#pragma unroll
    for (int ks = 0; ks < 4; ks++) {
#pragma unroll
        for (int njg = 0; njg < 2; njg++) {
            int rd = njg * 16 + rsel * 8 + rlo;
            int chunk = ks * 2 + csel;
            uint32_t r[4];
            ldsm_x4(r, Vs + rd * 128 + ((chunk ^ (rd & 7)) << 4));
            uint32_t b0[2] = {r[0], r[1]}, b1[2] = {r[2], r[3]};
            mma_bf16(o[0][njg * 2],     pa[0][ks], b0);
            mma_bf16(o[0][njg * 2 + 1], pa[0][ks], b1);
            mma_bf16(o[1][njg * 2],     pa[1][ks], b0);
            mma_bf16(o[1][njg * 2 + 1], pa[1][ks], b1);
        }
    }

    const int head = hp * 2 + whl;
    const size_t abase = ((size_t)b * 256 + head * 32) * HWC;
#pragma unroll
    for (int mi = 0; mi < 2; mi++) {
        const float inv0 = 1.f / rs[mi][0];
        const float inv1 = 1.f / rs[mi][1];
        const int t0 = mbase + mi * 16 + (lane >> 2);
        const size_t pos0 = (size_t)(h0 + (t0 >> 3)) * 256 + w0 + (t0 & 7);
        const size_t pos1 = pos0 + 256;
#pragma unroll
        for (int nj = 0; nj < 4; nj++) {
            const int d0 = nj * 8 + (lane & 3) * 2;
            __nv_bfloat16* p = attn + abase + (size_t)d0 * HWC;
            p[pos0]       = __float2bfloat16(o[mi][nj][0] * inv0);
            p[pos0 + HWC] = __float2bfloat16(o[mi][nj][1] * inv0);
            p[pos1]       = __float2bfloat16(o[mi][nj][2] * inv1);
            p[pos1 + HWC] = __float2bfloat16(o[mi][nj][3] * inv1);
        }
    }
}

// ---------------------------------------------------------------------------
// Launch
// ---------------------------------------------------------------------------
extern "C" void kernel_launch(void* const* d_in, const int* in_sizes, int n_in,
                              void* d_out, int out_size)
{
    const float* q    = (const float*)d_in[0];
    const float* gn_w = (const float*)d_in[1];
    const float* gn_b = (const float*)d_in[2];
    const float* q_w  = (const float*)d_in[3];
    const float* q_b  = (const float*)d_in[4];
    const float* k_w  = (const float*)d_in[5];
    const float* k_b  = (const float*)d_in[6];
    const float* v_w  = (const float*)d_in[7];
    const float* v_b  = (const float*)d_in[8];
    const float* o_w  = (const float*)d_in[9];
    const float* o_b  = (const float*)d_in[10];
    float* out = (float*)d_out;

    __nv_bfloat16 *p_wadjb, *p_owb, *p_qkv, *p_attn;
    float *p_badj;
    cudaGetSymbolAddress((void**)&p_wadjb, g_wadjb);
    cudaGetSymbolAddress((void**)&p_owb,   g_owb);
    cudaGetSymbolAddress((void**)&p_badj,  g_badj);
    cudaGetSymbolAddress((void**)&p_qkv,   g_qkv);
    cudaGetSymbolAddress((void**)&p_attn,  g_attn);

    cudaFuncSetAttribute((const void*)gemm_mma_kernel<6, false, float, __nv_bfloat16>,
                         cudaFuncAttributeMaxDynamicSharedMemorySize, SM_TOT);
    cudaFuncSetAttribute((const void*)gemm_mma_kernel<2, true, __nv_bfloat16, float>,
                         cudaFuncAttributeMaxDynamicSharedMemorySize, SM_TOT);

    // 1. GroupNorm stats
    gn_stats_kernel<<<NBAT * NGRP, 512>>>(q);

    // 2. Fold GN into QKV weights (bf16); o_w -> bf16
    prep_weights_kernel<<<dim3(768, NBAT), 256>>>(q_w, q_b, k_w, k_b, v_w, v_b, gn_w, gn_b);
    prep_ow_kernel<<<256, 256>>>(o_w);

    // 3. Fused (GN + QKV projection): [768 x 256] @ [256 x 65536] -> bf16
    gemm_mma_kernel<6, false, float, __nv_bfloat16><<<dim3(512, NBAT), 256, SM_TOT>>>(
        p_wadjb, 768LL * 256,
        p_badj, 768,
        q, (long long)CCH * HWC,
        p_qkv, 768LL * HWC,
        nullptr, 1.0f);

    // 4. Windowed attention (tensor-core)
    attn_mma_kernel<<<dim3(1024, 4, NBAT), 128>>>(p_qkv, p_attn);

    // 5. Output projection + residual + 2^-0.5 scale
    gemm_mma_kernel<2, true, __nv_bfloat16, float><<<dim3(512, NBAT), 256, SM_TOT>>>(
        p_owb, 0,
        o_b, 0,
        p_attn, (long long)CCH * HWC,
        out, (long long)CCH * HWC,
        q, 0.70710678118654752f);
}